// round 2
// baseline (speedup 1.0000x reference)
#include <cuda_runtime.h>
#include <math.h>

#define NN   10000
#define FIN  3000
#define HH1  500
#define HH2  64
#define NE   160000

// Output layout: (z1, z2, z3, pi, disp, mean, rec_adj, ret1) flattened fp32
static const long long Z1_OFF   = 0LL;
static const long long Z2_OFF   = 640000LL;
static const long long Z3_OFF   = 1280000LL;
static const long long PI_OFF   = 1920000LL;
static const long long DISP_OFF = 31920000LL;
static const long long MEAN_OFF = 61920000LL;
static const long long REC_OFF  = 91920000LL;
static const long long RET_OFF  = 191920000LL;

// -------- scratch (device globals; no allocations allowed) --------
__device__ float g_S   [NN * HH1];   // gcn1 support
__device__ float g_H   [NN * HH1];   // gcn1 aggregated (-> relu)
__device__ float g_XD  [NN * HH1];   // decoder hidden
__device__ float g_S2  [NN * HH2];   // gcn2 support
__device__ float g_EMB1[NN * HH2];
__device__ float g_EMB3[NN * HH2];
__device__ float g_ZN  [NN * HH2];
__device__ float g_VSUM[NN * HH2];
__device__ float g_G2  [NN * HH2];
__device__ float g_RSUM[NN];
__device__ float g_BNA [HH1];
__device__ float g_BNB [HH1];

// ============================================================
// Generic tiled SGEMM: C[M,N] = A[M,K] @ B[K,N], row-major.
// 64x64 tile, BK=16, 16x16 threads, 4x4 per thread.
// EPI: 0 none, 2 sigmoid(acc+bias), 3 clip(softplus(acc+bias)),
//      4 clip(exp(acc+bias)), 5 relu(scl*acc+bias)
// ============================================================
template<int EPI>
__global__ void sgemm_kernel(const float* __restrict__ A, const float* __restrict__ B,
                             float* __restrict__ C, int M, int N, int K,
                             const float* __restrict__ scl, const float* __restrict__ bias)
{
    __shared__ float As[64][17];
    __shared__ float Bs[16][64];
    const int tx = threadIdx.x, ty = threadIdx.y;
    const int tid = ty * 16 + tx;
    const int row0 = blockIdx.y * 64;
    const int col0 = blockIdx.x * 64;

    float acc[4][4];
    #pragma unroll
    for (int i = 0; i < 4; i++)
        #pragma unroll
        for (int j = 0; j < 4; j++) acc[i][j] = 0.f;

    const int ntiles = (K + 15) / 16;
    for (int t = 0; t < ntiles; t++) {
        const int k0 = t * 16;
        // load A tile 64x16 (4 elements per thread)
        #pragma unroll
        for (int p = 0; p < 4; p++) {
            int i  = (tid >> 4) + p * 16;
            int kk = (tid & 15);
            int ar = row0 + i, ak = k0 + kk;
            As[i][kk] = (ar < M && ak < K) ? A[(size_t)ar * K + ak] : 0.f;
        }
        // load B tile 16x64 (4 elements per thread), coalesced
        #pragma unroll
        for (int p = 0; p < 4; p++) {
            int kk = (tid >> 6) + p * 4;
            int j  = (tid & 63);
            int bk = k0 + kk, bc = col0 + j;
            Bs[kk][j] = (bk < K && bc < N) ? B[(size_t)bk * N + bc] : 0.f;
        }
        __syncthreads();

        #pragma unroll
        for (int kk = 0; kk < 16; kk++) {
            float a[4];
            #pragma unroll
            for (int i = 0; i < 4; i++) a[i] = As[ty * 4 + i][kk];
            float4 b4 = *reinterpret_cast<const float4*>(&Bs[kk][tx * 4]);
            float b[4] = {b4.x, b4.y, b4.z, b4.w};
            #pragma unroll
            for (int i = 0; i < 4; i++)
                #pragma unroll
                for (int j = 0; j < 4; j++)
                    acc[i][j] = fmaf(a[i], b[j], acc[i][j]);
        }
        __syncthreads();
    }

    #pragma unroll
    for (int i = 0; i < 4; i++) {
        int row = row0 + ty * 4 + i;
        if (row >= M) continue;
        #pragma unroll
        for (int j = 0; j < 4; j++) {
            int col = col0 + tx * 4 + j;
            if (col >= N) continue;
            float v = acc[i][j];
            if (EPI == 2) {
                v = 1.f / (1.f + expf(-(v + bias[col])));
            } else if (EPI == 3) {
                float x = v + bias[col];
                float sp = (x > 0.f) ? x + log1pf(expf(-x)) : log1pf(expf(x));
                v = fminf(fmaxf(sp, 1e-4f), 1e4f);
            } else if (EPI == 4) {
                float x = v + bias[col];
                v = fminf(fmaxf(expf(x), 1e-5f), 1e6f);
            } else if (EPI == 5) {
                v = fmaxf(fmaf(scl[col], v, bias[col]), 0.f);
            }
            C[(size_t)row * N + col] = v;
        }
    }
}

// ============================================================
// rec_adj = sigmoid(Z @ Z^T), Z [M,64]
// ============================================================
__global__ void recadj_kernel(const float* __restrict__ Z, float* __restrict__ C, int M)
{
    __shared__ float Ai[64][65];
    __shared__ float Bj[64][65];
    const int tx = threadIdx.x, ty = threadIdx.y;
    const int tid = ty * 16 + tx;
    const int r0 = blockIdx.y * 64;
    const int c0 = blockIdx.x * 64;

    #pragma unroll
    for (int p = 0; p < 16; p++) {
        int id = tid + p * 256;
        int i = id >> 6, k = id & 63;
        int ar = r0 + i;
        Ai[i][k] = (ar < M) ? Z[(size_t)ar * 64 + k] : 0.f;
        int br = c0 + i;
        Bj[i][k] = (br < M) ? Z[(size_t)br * 64 + k] : 0.f;
    }
    __syncthreads();

    float acc[4][4];
    #pragma unroll
    for (int i = 0; i < 4; i++)
        #pragma unroll
        for (int j = 0; j < 4; j++) acc[i][j] = 0.f;

    #pragma unroll 8
    for (int k = 0; k < 64; k++) {
        float a[4], b[4];
        #pragma unroll
        for (int i = 0; i < 4; i++) a[i] = Ai[ty * 4 + i][k];
        #pragma unroll
        for (int j = 0; j < 4; j++) b[j] = Bj[tx * 4 + j][k];
        #pragma unroll
        for (int i = 0; i < 4; i++)
            #pragma unroll
            for (int j = 0; j < 4; j++)
                acc[i][j] = fmaf(a[i], b[j], acc[i][j]);
    }

    #pragma unroll
    for (int i = 0; i < 4; i++) {
        int row = r0 + ty * 4 + i;
        if (row >= M) continue;
        #pragma unroll
        for (int j = 0; j < 4; j++) {
            int col = c0 + tx * 4 + j;
            if (col >= M) continue;
            C[(size_t)row * M + col] = 1.f / (1.f + expf(-acc[i][j]));
        }
    }
}

// ============================================================
// readout: vsum = G @ Emb  (G [M,K], Emb [K,64]) with fused row-sum of G
// ============================================================
__global__ void readout_kernel(const float* __restrict__ G, const float* __restrict__ Emb,
                               float* __restrict__ vsum, float* __restrict__ rsum,
                               int M, int K)
{
    __shared__ float As[64][17];
    __shared__ float Bs[16][64];
    const int tx = threadIdx.x, ty = threadIdx.y;
    const int tid = ty * 16 + tx;
    const int row0 = blockIdx.x * 64;

    float acc[4][4];
    float rs[4] = {0.f, 0.f, 0.f, 0.f};
    #pragma unroll
    for (int i = 0; i < 4; i++)
        #pragma unroll
        for (int j = 0; j < 4; j++) acc[i][j] = 0.f;

    const int ntiles = (K + 15) / 16;
    for (int t = 0; t < ntiles; t++) {
        const int k0 = t * 16;
        #pragma unroll
        for (int p = 0; p < 4; p++) {
            int i  = (tid >> 4) + p * 16;
            int kk = (tid & 15);
            int ar = row0 + i, ak = k0 + kk;
            As[i][kk] = (ar < M && ak < K) ? G[(size_t)ar * K + ak] : 0.f;
        }
        #pragma unroll
        for (int p = 0; p < 4; p++) {
            int kk = (tid >> 6) + p * 4;
            int j  = (tid & 63);
            int bk = k0 + kk;
            Bs[kk][j] = (bk < K) ? Emb[(size_t)bk * 64 + j] : 0.f;
        }
        __syncthreads();

        #pragma unroll
        for (int kk = 0; kk < 16; kk++) {
            float a[4];
            #pragma unroll
            for (int i = 0; i < 4; i++) a[i] = As[ty * 4 + i][kk];
            if (tx == 0) {
                #pragma unroll
                for (int i = 0; i < 4; i++) rs[i] += a[i];
            }
            float4 b4 = *reinterpret_cast<const float4*>(&Bs[kk][tx * 4]);
            float b[4] = {b4.x, b4.y, b4.z, b4.w};
            #pragma unroll
            for (int i = 0; i < 4; i++)
                #pragma unroll
                for (int j = 0; j < 4; j++)
                    acc[i][j] = fmaf(a[i], b[j], acc[i][j]);
        }
        __syncthreads();
    }

    #pragma unroll
    for (int i = 0; i < 4; i++) {
        int row = row0 + ty * 4 + i;
        if (row >= M) continue;
        #pragma unroll
        for (int j = 0; j < 4; j++) {
            int col = tx * 4 + j;
            vsum[(size_t)row * 64 + col] = acc[i][j];
        }
        if (tx == 0) rsum[row] = rs[i];
    }
}

// ============================================================
// sparse aggregation: out[rows[e],:] += vals[e] * S[cols[e],:]
// ============================================================
__global__ void agg_kernel_h1(const int* __restrict__ rows, const int* __restrict__ cols,
                              const float* __restrict__ vals, const float* __restrict__ S,
                              float* __restrict__ out)
{
    int e = blockIdx.x;
    int r = rows[e], c = cols[e];
    float v = vals[e];
    const float* src = S + (size_t)c * HH1;
    float* dst = out + (size_t)r * HH1;
    for (int h = threadIdx.x; h < HH1; h += blockDim.x)
        atomicAdd(&dst[h], v * src[h]);
}

__global__ void agg_kernel_h2(const int* __restrict__ rows, const int* __restrict__ cols,
                              const float* __restrict__ vals, const float* __restrict__ S,
                              float* __restrict__ out)
{
    int e = blockIdx.x;
    int r = rows[e], c = cols[e];
    float v = vals[e];
    int h = threadIdx.x;  // blockDim = 64
    atomicAdd(&out[(size_t)r * HH2 + h], v * S[(size_t)c * HH2 + h]);
}

// ============================================================
// elementwise helpers
// ============================================================
__global__ void zero_kernel(float4* __restrict__ p, long long n4)
{
    long long i = (long long)blockIdx.x * blockDim.x + threadIdx.x;
    if (i < n4) p[i] = make_float4(0.f, 0.f, 0.f, 0.f);
}

__global__ void relu_inplace_kernel(float* __restrict__ p, long long n)
{
    long long i = (long long)blockIdx.x * blockDim.x + threadIdx.x;
    if (i < n) p[i] = fmaxf(p[i], 0.f);
}

__global__ void relu_copy_kernel(const float* __restrict__ in, float* __restrict__ out, long long n)
{
    long long i = (long long)blockIdx.x * blockDim.x + threadIdx.x;
    if (i < n) out[i] = fmaxf(in[i], 0.f);
}

__global__ void bnprep_kernel(const float* __restrict__ gamma, const float* __restrict__ beta,
                              const float* __restrict__ mean, const float* __restrict__ var,
                              const float* __restrict__ bd, float* __restrict__ a, float* __restrict__ b)
{
    int j = blockIdx.x * blockDim.x + threadIdx.x;
    if (j >= HH1) return;
    float s = gamma[j] * rsqrtf(var[j] + 1e-5f);
    a[j] = s;
    b[j] = beta[j] + s * (bd[j] - mean[j]);
}

// l2-normalize 64-wide rows: one warp per row
__global__ void l2norm_kernel(const float* __restrict__ in, float* __restrict__ out, int M)
{
    int gw = (blockIdx.x * blockDim.x + threadIdx.x) >> 5;
    int lane = threadIdx.x & 31;
    if (gw >= M) return;
    float x0 = in[(size_t)gw * 64 + lane];
    float x1 = in[(size_t)gw * 64 + 32 + lane];
    float ss = x0 * x0 + x1 * x1;
    #pragma unroll
    for (int o = 16; o > 0; o >>= 1) ss += __shfl_xor_sync(0xffffffffu, ss, o);
    float d = fmaxf(sqrtf(ss), 1e-12f);
    out[(size_t)gw * 64 + lane]      = x0 / d;
    out[(size_t)gw * 64 + 32 + lane] = x1 / d;
}

// g2 = sigmoid(l2norm(vsum / rsum)): one warp per row
__global__ void g2_kernel(const float* __restrict__ vsum, const float* __restrict__ rsum,
                          float* __restrict__ g2, int M)
{
    int gw = (blockIdx.x * blockDim.x + threadIdx.x) >> 5;
    int lane = threadIdx.x & 31;
    if (gw >= M) return;
    float inv = 1.f / rsum[gw];
    float x0 = vsum[(size_t)gw * 64 + lane] * inv;
    float x1 = vsum[(size_t)gw * 64 + 32 + lane] * inv;
    float ss = x0 * x0 + x1 * x1;
    #pragma unroll
    for (int o = 16; o > 0; o >>= 1) ss += __shfl_xor_sync(0xffffffffu, ss, o);
    float d = fmaxf(sqrtf(ss), 1e-12f);
    g2[(size_t)gw * 64 + lane]      = 1.f / (1.f + expf(-x0 / d));
    g2[(size_t)gw * 64 + 32 + lane] = 1.f / (1.f + expf(-x1 / d));
}

// bilinear discriminator: sc = emb . (W @ g2row) + b, for emb1 and emb3
__global__ void disc_kernel(const float* __restrict__ emb1, const float* __restrict__ emb3,
                            const float* __restrict__ g2, const float* __restrict__ W,
                            const float* __restrict__ bptr, float* __restrict__ ret, int M)
{
    __shared__ float Ws[64][65];
    int tid = threadIdx.x;  // 256
    for (int id = tid; id < 4096; id += 256) {
        int d = id >> 6, e = id & 63;
        Ws[d][e] = W[id];
    }
    __syncthreads();

    int lane = tid & 31;
    int row = blockIdx.x * 8 + (tid >> 5);
    if (row >= M) return;

    float g0 = g2[(size_t)row * 64 + lane];
    float g1 = g2[(size_t)row * 64 + 32 + lane];
    float ulo = 0.f, uhi = 0.f;
    #pragma unroll
    for (int e = 0; e < 64; e++) {
        float ge = (e < 32) ? __shfl_sync(0xffffffffu, g0, e)
                            : __shfl_sync(0xffffffffu, g1, e - 32);
        ulo = fmaf(Ws[lane][e], ge, ulo);
        uhi = fmaf(Ws[lane + 32][e], ge, uhi);
    }
    float e10 = emb1[(size_t)row * 64 + lane];
    float e11 = emb1[(size_t)row * 64 + 32 + lane];
    float e30 = emb3[(size_t)row * 64 + lane];
    float e31 = emb3[(size_t)row * 64 + 32 + lane];
    float s1 = e10 * ulo + e11 * uhi;
    float s2 = e30 * ulo + e31 * uhi;
    #pragma unroll
    for (int o = 16; o > 0; o >>= 1) {
        s1 += __shfl_xor_sync(0xffffffffu, s1, o);
        s2 += __shfl_xor_sync(0xffffffffu, s2, o);
    }
    if (lane == 0) {
        float b = bptr[0];
        ret[(size_t)row * 2 + 0] = s1 + b;
        ret[(size_t)row * 2 + 1] = s2 + b;
    }
}

// ============================================================
// host launch
// ============================================================
static inline int cdiv(int a, int b) { return (a + b - 1) / b; }

extern "C" void kernel_launch(void* const* d_in, const int* in_sizes, int n_in,
                              void* d_out, int out_size)
{
    const float* feat     = (const float*)d_in[0];
    const float* feat_a   = (const float*)d_in[1];
    const float* feat_b   = (const float*)d_in[2];
    const int*   adj_rows = (const int*)  d_in[3];
    const int*   adj_cols = (const int*)  d_in[4];
    const float* adj_vals = (const float*)d_in[5];
    const float* graphN   = (const float*)d_in[6];
    const float* W1       = (const float*)d_in[7];
    const float* W2       = (const float*)d_in[8];
    const float* Wd       = (const float*)d_in[9];
    const float* bd       = (const float*)d_in[10];
    const float* bn_gamma = (const float*)d_in[11];
    const float* bn_beta  = (const float*)d_in[12];
    const float* bn_mean  = (const float*)d_in[13];
    const float* bn_var   = (const float*)d_in[14];
    const float* Wpi      = (const float*)d_in[15];
    const float* bpi      = (const float*)d_in[16];
    const float* Wdisp    = (const float*)d_in[17];
    const float* bdisp    = (const float*)d_in[18];
    const float* Wmean    = (const float*)d_in[19];
    const float* bmean    = (const float*)d_in[20];
    const float* disc_W   = (const float*)d_in[21];
    const float* disc_b   = (const float*)d_in[22];

    float* out = (float*)d_out;

    void *pS, *pH, *pXD, *pS2, *pE1, *pE3, *pZN, *pVS, *pG2, *pRS, *pBA, *pBB;
    cudaGetSymbolAddress(&pS,  g_S);
    cudaGetSymbolAddress(&pH,  g_H);
    cudaGetSymbolAddress(&pXD, g_XD);
    cudaGetSymbolAddress(&pS2, g_S2);
    cudaGetSymbolAddress(&pE1, g_EMB1);
    cudaGetSymbolAddress(&pE3, g_EMB3);
    cudaGetSymbolAddress(&pZN, g_ZN);
    cudaGetSymbolAddress(&pVS, g_VSUM);
    cudaGetSymbolAddress(&pG2, g_G2);
    cudaGetSymbolAddress(&pRS, g_RSUM);
    cudaGetSymbolAddress(&pBA, g_BNA);
    cudaGetSymbolAddress(&pBB, g_BNB);
    float* S   = (float*)pS;   float* H   = (float*)pH;
    float* XD  = (float*)pXD;  float* S2  = (float*)pS2;
    float* E1  = (float*)pE1;  float* E3  = (float*)pE3;
    float* ZN  = (float*)pZN;  float* VS  = (float*)pVS;
    float* G2  = (float*)pG2;  float* RS  = (float*)pRS;
    float* BA  = (float*)pBA;  float* BB  = (float*)pBB;

    const dim3 blk(16, 16);
    const int mt = cdiv(NN, 64);          // 157 row tiles

    // ---- encode(feat)->z1, encode(feat_a)->z2, encode(feat_b)->z3 ----
    const float* xs[3]   = {feat, feat_a, feat_b};
    const long long zo[3] = {Z1_OFF, Z2_OFF, Z3_OFF};
    for (int s = 0; s < 3; s++) {
        float* z = out + zo[s];
        // S = x @ W1
        sgemm_kernel<0><<<dim3(cdiv(HH1, 64), mt), blk>>>(xs[s], W1, S, NN, HH1, FIN, nullptr, nullptr);
        // H = segment_sum(vals * S[cols])
        {
            long long n4 = (long long)NN * HH1 / 4;
            zero_kernel<<<(unsigned)((n4 + 255) / 256), 256>>>((float4*)H, n4);
        }
        agg_kernel_h1<<<NE, 128>>>(adj_rows, adj_cols, adj_vals, S, H);
        relu_inplace_kernel<<<(unsigned)(((long long)NN * HH1 + 255) / 256), 256>>>(H, (long long)NN * HH1);
        // S2 = H @ W2
        sgemm_kernel<0><<<dim3(1, mt), blk>>>(H, W2, S2, NN, HH2, HH1, nullptr, nullptr);
        // z = segment_sum(vals * S2[cols])
        {
            long long n4 = (long long)NN * HH2 / 4;
            zero_kernel<<<(unsigned)((n4 + 255) / 256), 256>>>((float4*)z, n4);
        }
        agg_kernel_h2<<<NE, 64>>>(adj_rows, adj_cols, adj_vals, S2, z);
    }

    float* z1 = out + Z1_OFF;
    float* z3 = out + Z3_OFF;

    // ---- emb1 = relu(z1), emb3 = relu(z3) ----
    relu_copy_kernel<<<(unsigned)(((long long)NN * HH2 + 255) / 256), 256>>>(z1, E1, (long long)NN * HH2);
    relu_copy_kernel<<<(unsigned)(((long long)NN * HH2 + 255) / 256), 256>>>(z3, E3, (long long)NN * HH2);

    // ---- ZINB decoder ----
    bnprep_kernel<<<cdiv(HH1, 256), 256>>>(bn_gamma, bn_beta, bn_mean, bn_var, bd, BA, BB);
    sgemm_kernel<5><<<dim3(cdiv(HH1, 64), mt), blk>>>(z1, Wd, XD, NN, HH1, HH2, BA, BB);
    sgemm_kernel<2><<<dim3(cdiv(FIN, 64), mt), blk>>>(XD, Wpi,   out + PI_OFF,   NN, FIN, HH1, nullptr, bpi);
    sgemm_kernel<3><<<dim3(cdiv(FIN, 64), mt), blk>>>(XD, Wdisp, out + DISP_OFF, NN, FIN, HH1, nullptr, bdisp);
    sgemm_kernel<4><<<dim3(cdiv(FIN, 64), mt), blk>>>(XD, Wmean, out + MEAN_OFF, NN, FIN, HH1, nullptr, bmean);

    // ---- rec_adj = sigmoid(l2norm(z1) @ l2norm(z1)^T) ----
    l2norm_kernel<<<cdiv(NN * 32, 256), 256>>>(z1, ZN, NN);
    recadj_kernel<<<dim3(mt, mt), blk>>>(ZN, out + REC_OFF, NN);

    // ---- readout + discriminator ----
    readout_kernel<<<mt, blk>>>(graphN, E1, VS, RS, NN, NN);
    g2_kernel<<<cdiv(NN * 32, 256), 256>>>(VS, RS, G2, NN);
    disc_kernel<<<cdiv(NN, 8), 256>>>(E1, E3, G2, disc_W, disc_b, out + RET_OFF, NN);
}

// round 3
// speedup vs baseline: 1.0001x; 1.0001x over previous
#include <cuda_runtime.h>
#include <math.h>

#define NN   10000
#define FIN  3000
#define HH1  500
#define HH2  64
#define NE   160000

// Output layout: (z1, z2, z3, pi, disp, mean, rec_adj, ret1) flattened fp32
static const long long Z1_OFF   = 0LL;
static const long long Z2_OFF   = 640000LL;
static const long long Z3_OFF   = 1280000LL;
static const long long PI_OFF   = 1920000LL;
static const long long DISP_OFF = 31920000LL;
static const long long MEAN_OFF = 61920000LL;
static const long long REC_OFF  = 91920000LL;
static const long long RET_OFF  = 191920000LL;

// -------- scratch (device globals; no allocations allowed) --------
__device__ float g_S   [NN * HH1];   // gcn1 support
__device__ float g_H   [NN * HH1];   // gcn1 aggregated (-> relu)
__device__ float g_XD  [NN * HH1];   // decoder hidden
__device__ float g_S2  [NN * HH2];   // gcn2 support
__device__ float g_EMB1[NN * HH2];
__device__ float g_EMB3[NN * HH2];
__device__ float g_ZN  [NN * HH2];
__device__ float g_VSUM[NN * HH2];
__device__ float g_G2  [NN * HH2];
__device__ float g_RSUM[NN];
__device__ float g_BNA [HH1];
__device__ float g_BNB [HH1];

// ============================================================
// Generic tiled SGEMM: C[M,N] = A[M,K] @ B[K,N], row-major.
// 64x64 tile, BK=16, 16x16 threads, 4x4 per thread.
// EPI: 0 none, 2 sigmoid(acc+bias), 3 clip(softplus(acc+bias)),
//      4 clip(exp(acc+bias)), 5 relu(scl*acc+bias)
// ============================================================
template<int EPI>
__global__ void sgemm_kernel(const float* __restrict__ A, const float* __restrict__ B,
                             float* __restrict__ C, int M, int N, int K,
                             const float* __restrict__ scl, const float* __restrict__ bias)
{
    __shared__ float As[64][17];
    __shared__ float Bs[16][64];
    const int tx = threadIdx.x, ty = threadIdx.y;
    const int tid = ty * 16 + tx;
    const int row0 = blockIdx.y * 64;
    const int col0 = blockIdx.x * 64;

    float acc[4][4];
    #pragma unroll
    for (int i = 0; i < 4; i++)
        #pragma unroll
        for (int j = 0; j < 4; j++) acc[i][j] = 0.f;

    const int ntiles = (K + 15) / 16;
    for (int t = 0; t < ntiles; t++) {
        const int k0 = t * 16;
        // load A tile 64x16 (4 elements per thread)
        #pragma unroll
        for (int p = 0; p < 4; p++) {
            int i  = (tid >> 4) + p * 16;
            int kk = (tid & 15);
            int ar = row0 + i, ak = k0 + kk;
            As[i][kk] = (ar < M && ak < K) ? A[(size_t)ar * K + ak] : 0.f;
        }
        // load B tile 16x64 (4 elements per thread), coalesced
        #pragma unroll
        for (int p = 0; p < 4; p++) {
            int kk = (tid >> 6) + p * 4;
            int j  = (tid & 63);
            int bk = k0 + kk, bc = col0 + j;
            Bs[kk][j] = (bk < K && bc < N) ? B[(size_t)bk * N + bc] : 0.f;
        }
        __syncthreads();

        #pragma unroll
        for (int kk = 0; kk < 16; kk++) {
            float a[4];
            #pragma unroll
            for (int i = 0; i < 4; i++) a[i] = As[ty * 4 + i][kk];
            float4 b4 = *reinterpret_cast<const float4*>(&Bs[kk][tx * 4]);
            float b[4] = {b4.x, b4.y, b4.z, b4.w};
            #pragma unroll
            for (int i = 0; i < 4; i++)
                #pragma unroll
                for (int j = 0; j < 4; j++)
                    acc[i][j] = fmaf(a[i], b[j], acc[i][j]);
        }
        __syncthreads();
    }

    #pragma unroll
    for (int i = 0; i < 4; i++) {
        int row = row0 + ty * 4 + i;
        if (row >= M) continue;
        #pragma unroll
        for (int j = 0; j < 4; j++) {
            int col = col0 + tx * 4 + j;
            if (col >= N) continue;
            float v = acc[i][j];
            if (EPI == 2) {
                v = 1.f / (1.f + expf(-(v + bias[col])));
            } else if (EPI == 3) {
                float x = v + bias[col];
                float sp = (x > 0.f) ? x + log1pf(expf(-x)) : log1pf(expf(x));
                v = fminf(fmaxf(sp, 1e-4f), 1e4f);
            } else if (EPI == 4) {
                float x = v + bias[col];
                v = fminf(fmaxf(expf(x), 1e-5f), 1e6f);
            } else if (EPI == 5) {
                v = fmaxf(fmaf(scl[col], v, bias[col]), 0.f);
            }
            C[(size_t)row * N + col] = v;
        }
    }
}

// ============================================================
// rec_adj = sigmoid(Z @ Z^T), Z [M,64]
// ============================================================
__global__ void recadj_kernel(const float* __restrict__ Z, float* __restrict__ C, int M)
{
    __shared__ float Ai[64][65];
    __shared__ float Bj[64][65];
    const int tx = threadIdx.x, ty = threadIdx.y;
    const int tid = ty * 16 + tx;
    const int r0 = blockIdx.y * 64;
    const int c0 = blockIdx.x * 64;

    #pragma unroll
    for (int p = 0; p < 16; p++) {
        int id = tid + p * 256;
        int i = id >> 6, k = id & 63;
        int ar = r0 + i;
        Ai[i][k] = (ar < M) ? Z[(size_t)ar * 64 + k] : 0.f;
        int br = c0 + i;
        Bj[i][k] = (br < M) ? Z[(size_t)br * 64 + k] : 0.f;
    }
    __syncthreads();

    float acc[4][4];
    #pragma unroll
    for (int i = 0; i < 4; i++)
        #pragma unroll
        for (int j = 0; j < 4; j++) acc[i][j] = 0.f;

    #pragma unroll 8
    for (int k = 0; k < 64; k++) {
        float a[4], b[4];
        #pragma unroll
        for (int i = 0; i < 4; i++) a[i] = Ai[ty * 4 + i][k];
        #pragma unroll
        for (int j = 0; j < 4; j++) b[j] = Bj[tx * 4 + j][k];
        #pragma unroll
        for (int i = 0; i < 4; i++)
            #pragma unroll
            for (int j = 0; j < 4; j++)
                acc[i][j] = fmaf(a[i], b[j], acc[i][j]);
    }

    #pragma unroll
    for (int i = 0; i < 4; i++) {
        int row = r0 + ty * 4 + i;
        if (row >= M) continue;
        #pragma unroll
        for (int j = 0; j < 4; j++) {
            int col = c0 + tx * 4 + j;
            if (col >= M) continue;
            C[(size_t)row * M + col] = 1.f / (1.f + expf(-acc[i][j]));
        }
    }
}

// ============================================================
// readout: vsum = G @ Emb  (G [M,K], Emb [K,64]) with fused row-sum of G
// ============================================================
__global__ void readout_kernel(const float* __restrict__ G, const float* __restrict__ Emb,
                               float* __restrict__ vsum, float* __restrict__ rsum,
                               int M, int K)
{
    __shared__ float As[64][17];
    __shared__ float Bs[16][64];
    const int tx = threadIdx.x, ty = threadIdx.y;
    const int tid = ty * 16 + tx;
    const int row0 = blockIdx.x * 64;

    float acc[4][4];
    float rs[4] = {0.f, 0.f, 0.f, 0.f};
    #pragma unroll
    for (int i = 0; i < 4; i++)
        #pragma unroll
        for (int j = 0; j < 4; j++) acc[i][j] = 0.f;

    const int ntiles = (K + 15) / 16;
    for (int t = 0; t < ntiles; t++) {
        const int k0 = t * 16;
        #pragma unroll
        for (int p = 0; p < 4; p++) {
            int i  = (tid >> 4) + p * 16;
            int kk = (tid & 15);
            int ar = row0 + i, ak = k0 + kk;
            As[i][kk] = (ar < M && ak < K) ? G[(size_t)ar * K + ak] : 0.f;
        }
        #pragma unroll
        for (int p = 0; p < 4; p++) {
            int kk = (tid >> 6) + p * 4;
            int j  = (tid & 63);
            int bk = k0 + kk;
            Bs[kk][j] = (bk < K) ? Emb[(size_t)bk * 64 + j] : 0.f;
        }
        __syncthreads();

        #pragma unroll
        for (int kk = 0; kk < 16; kk++) {
            float a[4];
            #pragma unroll
            for (int i = 0; i < 4; i++) a[i] = As[ty * 4 + i][kk];
            if (tx == 0) {
                #pragma unroll
                for (int i = 0; i < 4; i++) rs[i] += a[i];
            }
            float4 b4 = *reinterpret_cast<const float4*>(&Bs[kk][tx * 4]);
            float b[4] = {b4.x, b4.y, b4.z, b4.w};
            #pragma unroll
            for (int i = 0; i < 4; i++)
                #pragma unroll
                for (int j = 0; j < 4; j++)
                    acc[i][j] = fmaf(a[i], b[j], acc[i][j]);
        }
        __syncthreads();
    }

    #pragma unroll
    for (int i = 0; i < 4; i++) {
        int row = row0 + ty * 4 + i;
        if (row >= M) continue;
        #pragma unroll
        for (int j = 0; j < 4; j++) {
            int col = tx * 4 + j;
            vsum[(size_t)row * 64 + col] = acc[i][j];
        }
        if (tx == 0) rsum[row] = rs[i];
    }
}

// ============================================================
// sparse aggregation: out[rows[e],:] += vals[e] * S[cols[e],:]
// ============================================================
__global__ void agg_kernel_h1(const int* __restrict__ rows, const int* __restrict__ cols,
                              const float* __restrict__ vals, const float* __restrict__ S,
                              float* __restrict__ out)
{
    int e = blockIdx.x;
    int r = rows[e], c = cols[e];
    float v = vals[e];
    const float* src = S + (size_t)c * HH1;
    float* dst = out + (size_t)r * HH1;
    for (int h = threadIdx.x; h < HH1; h += blockDim.x)
        atomicAdd(&dst[h], v * src[h]);
}

__global__ void agg_kernel_h2(const int* __restrict__ rows, const int* __restrict__ cols,
                              const float* __restrict__ vals, const float* __restrict__ S,
                              float* __restrict__ out)
{
    int e = blockIdx.x;
    int r = rows[e], c = cols[e];
    float v = vals[e];
    int h = threadIdx.x;  // blockDim = 64
    atomicAdd(&out[(size_t)r * HH2 + h], v * S[(size_t)c * HH2 + h]);
}

// ============================================================
// elementwise helpers
// ============================================================
__global__ void zero_kernel(float4* __restrict__ p, long long n4)
{
    long long i = (long long)blockIdx.x * blockDim.x + threadIdx.x;
    if (i < n4) p[i] = make_float4(0.f, 0.f, 0.f, 0.f);
}

__global__ void relu_inplace_kernel(float* __restrict__ p, long long n)
{
    long long i = (long long)blockIdx.x * blockDim.x + threadIdx.x;
    if (i < n) p[i] = fmaxf(p[i], 0.f);
}

__global__ void relu_copy_kernel(const float* __restrict__ in, float* __restrict__ out, long long n)
{
    long long i = (long long)blockIdx.x * blockDim.x + threadIdx.x;
    if (i < n) out[i] = fmaxf(in[i], 0.f);
}

__global__ void bnprep_kernel(const float* __restrict__ gamma, const float* __restrict__ beta,
                              const float* __restrict__ mean, const float* __restrict__ var,
                              const float* __restrict__ bd, float* __restrict__ a, float* __restrict__ b)
{
    int j = blockIdx.x * blockDim.x + threadIdx.x;
    if (j >= HH1) return;
    float s = gamma[j] * rsqrtf(var[j] + 1e-5f);
    a[j] = s;
    b[j] = beta[j] + s * (bd[j] - mean[j]);
}

// l2-normalize 64-wide rows: one warp per row
__global__ void l2norm_kernel(const float* __restrict__ in, float* __restrict__ out, int M)
{
    int gw = (blockIdx.x * blockDim.x + threadIdx.x) >> 5;
    int lane = threadIdx.x & 31;
    if (gw >= M) return;
    float x0 = in[(size_t)gw * 64 + lane];
    float x1 = in[(size_t)gw * 64 + 32 + lane];
    float ss = x0 * x0 + x1 * x1;
    #pragma unroll
    for (int o = 16; o > 0; o >>= 1) ss += __shfl_xor_sync(0xffffffffu, ss, o);
    float d = fmaxf(sqrtf(ss), 1e-12f);
    out[(size_t)gw * 64 + lane]      = x0 / d;
    out[(size_t)gw * 64 + 32 + lane] = x1 / d;
}

// g2 = sigmoid(l2norm(vsum / rsum)): one warp per row
__global__ void g2_kernel(const float* __restrict__ vsum, const float* __restrict__ rsum,
                          float* __restrict__ g2, int M)
{
    int gw = (blockIdx.x * blockDim.x + threadIdx.x) >> 5;
    int lane = threadIdx.x & 31;
    if (gw >= M) return;
    float inv = 1.f / rsum[gw];
    float x0 = vsum[(size_t)gw * 64 + lane] * inv;
    float x1 = vsum[(size_t)gw * 64 + 32 + lane] * inv;
    float ss = x0 * x0 + x1 * x1;
    #pragma unroll
    for (int o = 16; o > 0; o >>= 1) ss += __shfl_xor_sync(0xffffffffu, ss, o);
    float d = fmaxf(sqrtf(ss), 1e-12f);
    g2[(size_t)gw * 64 + lane]      = 1.f / (1.f + expf(-x0 / d));
    g2[(size_t)gw * 64 + 32 + lane] = 1.f / (1.f + expf(-x1 / d));
}

// bilinear discriminator: sc = emb . (W @ g2row) + b, for emb1 and emb3
__global__ void disc_kernel(const float* __restrict__ emb1, const float* __restrict__ emb3,
                            const float* __restrict__ g2, const float* __restrict__ W,
                            const float* __restrict__ bptr, float* __restrict__ ret, int M)
{
    __shared__ float Ws[64][65];
    int tid = threadIdx.x;  // 256
    for (int id = tid; id < 4096; id += 256) {
        int d = id >> 6, e = id & 63;
        Ws[d][e] = W[id];
    }
    __syncthreads();

    int lane = tid & 31;
    int row = blockIdx.x * 8 + (tid >> 5);
    if (row >= M) return;

    float g0 = g2[(size_t)row * 64 + lane];
    float g1 = g2[(size_t)row * 64 + 32 + lane];
    float ulo = 0.f, uhi = 0.f;
    #pragma unroll
    for (int e = 0; e < 64; e++) {
        float ge = (e < 32) ? __shfl_sync(0xffffffffu, g0, e)
                            : __shfl_sync(0xffffffffu, g1, e - 32);
        ulo = fmaf(Ws[lane][e], ge, ulo);
        uhi = fmaf(Ws[lane + 32][e], ge, uhi);
    }
    float e10 = emb1[(size_t)row * 64 + lane];
    float e11 = emb1[(size_t)row * 64 + 32 + lane];
    float e30 = emb3[(size_t)row * 64 + lane];
    float e31 = emb3[(size_t)row * 64 + 32 + lane];
    float s1 = e10 * ulo + e11 * uhi;
    float s2 = e30 * ulo + e31 * uhi;
    #pragma unroll
    for (int o = 16; o > 0; o >>= 1) {
        s1 += __shfl_xor_sync(0xffffffffu, s1, o);
        s2 += __shfl_xor_sync(0xffffffffu, s2, o);
    }
    if (lane == 0) {
        float b = bptr[0];
        ret[(size_t)row * 2 + 0] = s1 + b;
        ret[(size_t)row * 2 + 1] = s2 + b;
    }
}

// ============================================================
// host launch
// ============================================================
static inline int cdiv(int a, int b) { return (a + b - 1) / b; }

extern "C" void kernel_launch(void* const* d_in, const int* in_sizes, int n_in,
                              void* d_out, int out_size)
{
    const float* feat     = (const float*)d_in[0];
    const float* feat_a   = (const float*)d_in[1];
    const float* feat_b   = (const float*)d_in[2];
    const int*   adj_rows = (const int*)  d_in[3];
    const int*   adj_cols = (const int*)  d_in[4];
    const float* adj_vals = (const float*)d_in[5];
    const float* graphN   = (const float*)d_in[6];
    const float* W1       = (const float*)d_in[7];
    const float* W2       = (const float*)d_in[8];
    const float* Wd       = (const float*)d_in[9];
    const float* bd       = (const float*)d_in[10];
    const float* bn_gamma = (const float*)d_in[11];
    const float* bn_beta  = (const float*)d_in[12];
    const float* bn_mean  = (const float*)d_in[13];
    const float* bn_var   = (const float*)d_in[14];
    const float* Wpi      = (const float*)d_in[15];
    const float* bpi      = (const float*)d_in[16];
    const float* Wdisp    = (const float*)d_in[17];
    const float* bdisp    = (const float*)d_in[18];
    const float* Wmean    = (const float*)d_in[19];
    const float* bmean    = (const float*)d_in[20];
    const float* disc_W   = (const float*)d_in[21];
    const float* disc_b   = (const float*)d_in[22];

    float* out = (float*)d_out;

    void *pS, *pH, *pXD, *pS2, *pE1, *pE3, *pZN, *pVS, *pG2, *pRS, *pBA, *pBB;
    cudaGetSymbolAddress(&pS,  g_S);
    cudaGetSymbolAddress(&pH,  g_H);
    cudaGetSymbolAddress(&pXD, g_XD);
    cudaGetSymbolAddress(&pS2, g_S2);
    cudaGetSymbolAddress(&pE1, g_EMB1);
    cudaGetSymbolAddress(&pE3, g_EMB3);
    cudaGetSymbolAddress(&pZN, g_ZN);
    cudaGetSymbolAddress(&pVS, g_VSUM);
    cudaGetSymbolAddress(&pG2, g_G2);
    cudaGetSymbolAddress(&pRS, g_RSUM);
    cudaGetSymbolAddress(&pBA, g_BNA);
    cudaGetSymbolAddress(&pBB, g_BNB);
    float* S   = (float*)pS;   float* H   = (float*)pH;
    float* XD  = (float*)pXD;  float* S2  = (float*)pS2;
    float* E1  = (float*)pE1;  float* E3  = (float*)pE3;
    float* ZN  = (float*)pZN;  float* VS  = (float*)pVS;
    float* G2  = (float*)pG2;  float* RS  = (float*)pRS;
    float* BA  = (float*)pBA;  float* BB  = (float*)pBB;

    const dim3 blk(16, 16);
    const int mt = cdiv(NN, 64);          // 157 row tiles

    // ---- encode(feat)->z1, encode(feat_a)->z2, encode(feat_b)->z3 ----
    const float* xs[3]   = {feat, feat_a, feat_b};
    const long long zo[3] = {Z1_OFF, Z2_OFF, Z3_OFF};
    for (int s = 0; s < 3; s++) {
        float* z = out + zo[s];
        // S = x @ W1
        sgemm_kernel<0><<<dim3(cdiv(HH1, 64), mt), blk>>>(xs[s], W1, S, NN, HH1, FIN, nullptr, nullptr);
        // H = segment_sum(vals * S[cols])
        {
            long long n4 = (long long)NN * HH1 / 4;
            zero_kernel<<<(unsigned)((n4 + 255) / 256), 256>>>((float4*)H, n4);
        }
        agg_kernel_h1<<<NE, 128>>>(adj_rows, adj_cols, adj_vals, S, H);
        relu_inplace_kernel<<<(unsigned)(((long long)NN * HH1 + 255) / 256), 256>>>(H, (long long)NN * HH1);
        // S2 = H @ W2
        sgemm_kernel<0><<<dim3(1, mt), blk>>>(H, W2, S2, NN, HH2, HH1, nullptr, nullptr);
        // z = segment_sum(vals * S2[cols])
        {
            long long n4 = (long long)NN * HH2 / 4;
            zero_kernel<<<(unsigned)((n4 + 255) / 256), 256>>>((float4*)z, n4);
        }
        agg_kernel_h2<<<NE, 64>>>(adj_rows, adj_cols, adj_vals, S2, z);
    }

    float* z1 = out + Z1_OFF;
    float* z3 = out + Z3_OFF;

    // ---- emb1 = relu(z1), emb3 = relu(z3) ----
    relu_copy_kernel<<<(unsigned)(((long long)NN * HH2 + 255) / 256), 256>>>(z1, E1, (long long)NN * HH2);
    relu_copy_kernel<<<(unsigned)(((long long)NN * HH2 + 255) / 256), 256>>>(z3, E3, (long long)NN * HH2);

    // ---- ZINB decoder ----
    bnprep_kernel<<<cdiv(HH1, 256), 256>>>(bn_gamma, bn_beta, bn_mean, bn_var, bd, BA, BB);
    sgemm_kernel<5><<<dim3(cdiv(HH1, 64), mt), blk>>>(z1, Wd, XD, NN, HH1, HH2, BA, BB);
    sgemm_kernel<2><<<dim3(cdiv(FIN, 64), mt), blk>>>(XD, Wpi,   out + PI_OFF,   NN, FIN, HH1, nullptr, bpi);
    sgemm_kernel<3><<<dim3(cdiv(FIN, 64), mt), blk>>>(XD, Wdisp, out + DISP_OFF, NN, FIN, HH1, nullptr, bdisp);
    sgemm_kernel<4><<<dim3(cdiv(FIN, 64), mt), blk>>>(XD, Wmean, out + MEAN_OFF, NN, FIN, HH1, nullptr, bmean);

    // ---- rec_adj = sigmoid(l2norm(z1) @ l2norm(z1)^T) ----
    l2norm_kernel<<<cdiv(NN * 32, 256), 256>>>(z1, ZN, NN);
    recadj_kernel<<<dim3(mt, mt), blk>>>(ZN, out + REC_OFF, NN);

    // ---- readout + discriminator ----
    readout_kernel<<<mt, blk>>>(graphN, E1, VS, RS, NN, NN);
    g2_kernel<<<cdiv(NN * 32, 256), 256>>>(VS, RS, G2, NN);
    disc_kernel<<<cdiv(NN, 8), 256>>>(E1, E3, G2, disc_W, disc_b, out + RET_OFF, NN);
}

// round 8
// speedup vs baseline: 1.6354x; 1.6353x over previous
#include <cuda_runtime.h>
#include <cuda_bf16.h>
#include <math.h>
#include <stdint.h>

#define NN   10000
#define FIN  3000
#define HH1  500
#define HH2  64
#define NE   160000
#define KP_FIN 3008
#define KP_H1  512
#define KP_N   10048
#define NP_W1  512
#define NP_DEC 3072

static const long long Z1_OFF   = 0LL;
static const long long Z2_OFF   = 640000LL;
static const long long Z3_OFF   = 1280000LL;
static const long long PI_OFF   = 1920000LL;
static const long long DISP_OFF = 31920000LL;
static const long long MEAN_OFF = 61920000LL;
static const long long REC_OFF  = 91920000LL;
static const long long RET_OFF  = 191920000LL;

__device__ float g_S   [NN * HH1];
__device__ float g_H   [NN * HH1];
__device__ float g_XD  [NN * HH1];
__device__ float g_S2  [NN * HH2];
__device__ float g_EMB1[NN * HH2];
__device__ float g_EMB3[NN * HH2];
__device__ float g_VSUM[NN * HH2];
__device__ float g_G2  [NN * HH2];
__device__ float g_RSUM[NN];
__device__ float g_BNA [HH1];
__device__ float g_BNB [HH1];
__device__ __nv_bfloat16 g_Ah[(size_t)NN * KP_FIN];
__device__ __nv_bfloat16 g_Al[(size_t)NN * KP_FIN];
__device__ __nv_bfloat16 g_W1th[(size_t)NP_W1 * KP_FIN];
__device__ __nv_bfloat16 g_W1tl[(size_t)NP_W1 * KP_FIN];
__device__ __nv_bfloat16 g_XDh[(size_t)NN * KP_H1];
__device__ __nv_bfloat16 g_XDl[(size_t)NN * KP_H1];
__device__ __nv_bfloat16 g_Wpith[(size_t)NP_DEC * KP_H1];
__device__ __nv_bfloat16 g_Wpitl[(size_t)NP_DEC * KP_H1];
__device__ __nv_bfloat16 g_Wdth [(size_t)NP_DEC * KP_H1];
__device__ __nv_bfloat16 g_Wdtl [(size_t)NP_DEC * KP_H1];
__device__ __nv_bfloat16 g_Wmth [(size_t)NP_DEC * KP_H1];
__device__ __nv_bfloat16 g_Wmtl [(size_t)NP_DEC * KP_H1];
__device__ __nv_bfloat16 g_Gh[(size_t)NN * KP_N];
__device__ __nv_bfloat16 g_E1th[(size_t)64 * KP_N];
__device__ __nv_bfloat16 g_E1tl[(size_t)64 * KP_N];
__device__ __nv_bfloat16 g_ZNh[(size_t)NN * 64];
__device__ __nv_bfloat16 g_ZNl[(size_t)NN * 64];

// ---------------- helpers ----------------
__device__ __forceinline__ uint32_t smem_u32(const void* p) {
    uint32_t a;
    asm("{ .reg .u64 t; cvta.to.shared.u64 t, %1; cvt.u32.u64 %0, t; }" : "=r"(a) : "l"(p));
    return a;
}
__device__ __forceinline__ void cpa16(uint32_t saddr, const void* g, bool pred) {
    int sz = pred ? 16 : 0;
    asm volatile("cp.async.cg.shared.global [%0], [%1], 16, %2;" :: "r"(saddr), "l"(g), "r"(sz) : "memory");
}
__device__ __forceinline__ void mma16816(float* d, const uint32_t* a, const uint32_t* b) {
    asm volatile(
        "mma.sync.aligned.m16n8k16.row.col.f32.bf16.bf16.f32 "
        "{%0,%1,%2,%3}, {%4,%5,%6,%7}, {%8,%9}, {%0,%1,%2,%3};"
        : "+f"(d[0]), "+f"(d[1]), "+f"(d[2]), "+f"(d[3])
        : "r"(a[0]), "r"(a[1]), "r"(a[2]), "r"(a[3]), "r"(b[0]), "r"(b[1]));
}
template<int EPI>
__device__ __forceinline__ float epi_apply(float v, const float* __restrict__ bias, int gc) {
    if (EPI == 2) {
        float x = v + (bias ? bias[gc] : 0.f);
        return 1.f / (1.f + expf(-x));
    } else if (EPI == 3) {
        float x = v + bias[gc];
        float sp = (x > 0.f) ? x + log1pf(expf(-x)) : log1pf(expf(x));
        return fminf(fmaxf(sp, 1e-4f), 1e4f);
    } else if (EPI == 4) {
        return fminf(fmaxf(expf(v + bias[gc]), 1e-5f), 1e6f);
    }
    return v;
}

// ============================================================
// bf16-split mma.sync GEMM: C[M,Nreal] = A[M,Kp] @ Bt[NB,Kp]^T
// BM=128, BK=32, 256 threads (8 warps, 2x4), warp tile 64 x BN/4.
// NPASS=3: Ah*Bh + Ah*Bl + Al*Bh.  NPASS=2: Ah*Bh + Ah*Bl.
// ============================================================
template<int BN, int EPI, int NPASS>
__global__ void __launch_bounds__(256) gemm_mma(
    const __nv_bfloat16* __restrict__ Ah, const __nv_bfloat16* __restrict__ Al, int lda,
    const __nv_bfloat16* __restrict__ Bh, const __nv_bfloat16* __restrict__ Bl, int ldb, int NB,
    float* __restrict__ C, int ldc, int M, int Nreal, int Kp,
    const float* __restrict__ bias)
{
    constexpr int WN = BN / 4;    // warp N extent
    constexpr int NT = WN / 8;    // n-tiles per warp
    __shared__ __align__(16) __nv_bfloat16 As[2][128][40];
    __shared__ __align__(16) __nv_bfloat16 Bs[2][BN][40];

    const int tid = threadIdx.x;
    const int wid = tid >> 5, lane = tid & 31;
    const int wm = wid >> 2, wn = wid & 3;
    const int row0 = blockIdx.y * 128, col0 = blockIdx.x * BN;

    const __nv_bfloat16* APP[3] = {Ah, Ah, Al};
    const __nv_bfloat16* BPP[3] = {Bh, Bl, Bh};
    const int KT = Kp >> 5;
    const int S = KT * NPASS;

    float acc[4][NT][4];
    #pragma unroll
    for (int i = 0; i < 4; i++)
        #pragma unroll
        for (int j = 0; j < NT; j++)
            #pragma unroll
            for (int k = 0; k < 4; k++) acc[i][j][k] = 0.f;

    auto load_stage = [&](int s) {
        const int buf = s & 1;
        const int pass = s / KT;
        const int k0 = (s - pass * KT) << 5;
        const __nv_bfloat16* Ap = APP[pass];
        const __nv_bfloat16* Bp = BPP[pass];
        #pragma unroll
        for (int g = tid; g < 512; g += 256) {
            int r = g >> 2, ch = g & 3;
            int gr = row0 + r;
            bool p = (gr < M); if (!p) gr = 0;
            cpa16(smem_u32(&As[buf][r][ch * 8]), Ap + (size_t)gr * lda + k0 + ch * 8, p);
        }
        #pragma unroll
        for (int g = tid; g < BN * 4; g += 256) {
            int n = g >> 2, ch = g & 3;
            int gn = col0 + n;
            bool p = (gn < NB); if (!p) gn = 0;
            cpa16(smem_u32(&Bs[buf][n][ch * 8]), Bp + (size_t)gn * ldb + k0 + ch * 8, p);
        }
        asm volatile("cp.async.commit_group;" ::: "memory");
    };

    load_stage(0);
    for (int s = 0; s < S; s++) {
        asm volatile("cp.async.wait_group 0;" ::: "memory");
        __syncthreads();
        if (s + 1 < S) load_stage(s + 1);
        const int buf = s & 1;
        #pragma unroll
        for (int kk = 0; kk < 2; kk++) {
            uint32_t af[4][4];
            #pragma unroll
            for (int mi = 0; mi < 4; mi++) {
                int r = wm * 64 + mi * 16 + (lane >> 2);
                int c = (lane & 3) * 2 + kk * 16;
                af[mi][0] = *(const uint32_t*)&As[buf][r][c];
                af[mi][1] = *(const uint32_t*)&As[buf][r + 8][c];
                af[mi][2] = *(const uint32_t*)&As[buf][r][c + 8];
                af[mi][3] = *(const uint32_t*)&As[buf][r + 8][c + 8];
            }
            uint32_t bfr[NT][2];
            #pragma unroll
            for (int ni = 0; ni < NT; ni++) {
                int n = wn * WN + ni * 8 + (lane >> 2);
                int kb = (lane & 3) * 2 + kk * 16;
                bfr[ni][0] = *(const uint32_t*)&Bs[buf][n][kb];
                bfr[ni][1] = *(const uint32_t*)&Bs[buf][n][kb + 8];
            }
            #pragma unroll
            for (int mi = 0; mi < 4; mi++)
                #pragma unroll
                for (int ni = 0; ni < NT; ni++)
                    mma16816(acc[mi][ni], af[mi], bfr[ni]);
        }
        __syncthreads();
    }

    // epilogue: d0,d1 -> (r, c), (r, c+1); d2,d3 -> (r+8, ...)
    #pragma unroll
    for (int mi = 0; mi < 4; mi++) {
        #pragma unroll
        for (int ni = 0; ni < NT; ni++) {
            int gr = row0 + wm * 64 + mi * 16 + (lane >> 2);
            int gc = col0 + wn * WN + ni * 8 + (lane & 3) * 2;
            #pragma unroll
            for (int h = 0; h < 2; h++) {
                int r = gr + h * 8;
                if (r < M) {
                    if (gc < Nreal)
                        C[(size_t)r * ldc + gc] = epi_apply<EPI>(acc[mi][ni][2 * h], bias, gc);
                    if (gc + 1 < Nreal)
                        C[(size_t)r * ldc + gc + 1] = epi_apply<EPI>(acc[mi][ni][2 * h + 1], bias, gc + 1);
                }
            }
        }
    }
}

// ---------------- conversions ----------------
__global__ void conv_rows(const float* __restrict__ in, int K, int Kp,
                          __nv_bfloat16* __restrict__ hi, __nv_bfloat16* __restrict__ lo,
                          float* __restrict__ rsum)
{
    const int r = blockIdx.x;
    const float* src = in + (size_t)r * K;
    const size_t o = (size_t)r * Kp;
    float s = 0.f;
    for (int c = threadIdx.x; c < Kp; c += 256) {
        float v = (c < K) ? src[c] : 0.f;
        s += v;
        __nv_bfloat16 h = __float2bfloat16(v);
        hi[o + c] = h;
        if (lo) lo[o + c] = __float2bfloat16(v - __bfloat162float(h));
    }
    if (rsum) {
        __shared__ float red[256];
        red[threadIdx.x] = s; __syncthreads();
        for (int st = 128; st > 0; st >>= 1) {
            if (threadIdx.x < st) red[threadIdx.x] += red[threadIdx.x + st];
            __syncthreads();
        }
        if (threadIdx.x == 0) rsum[r] = red[0];
    }
}
__global__ void conv_transpose(const float* __restrict__ W, int K, int N, int Kp, int Np,
                               __nv_bfloat16* __restrict__ hi, __nv_bfloat16* __restrict__ lo,
                               int do_relu)
{
    long long idx = (long long)blockIdx.x * blockDim.x + threadIdx.x;
    if (idx >= (long long)Np * Kp) return;
    int n = (int)(idx / Kp), k = (int)(idx % Kp);
    float v = (n < N && k < K) ? W[(size_t)k * N + n] : 0.f;
    if (do_relu) v = fmaxf(v, 0.f);
    __nv_bfloat16 h = __float2bfloat16(v);
    hi[idx] = h;
    lo[idx] = __float2bfloat16(v - __bfloat162float(h));
}
__global__ void znconv_kernel(const float* __restrict__ z1,
                              __nv_bfloat16* __restrict__ hi, __nv_bfloat16* __restrict__ lo, int M)
{
    int gw = (blockIdx.x * blockDim.x + threadIdx.x) >> 5;
    int lane = threadIdx.x & 31;
    if (gw >= M) return;
    float x0 = z1[(size_t)gw * 64 + lane];
    float x1 = z1[(size_t)gw * 64 + 32 + lane];
    float ss = x0 * x0 + x1 * x1;
    #pragma unroll
    for (int o = 16; o > 0; o >>= 1) ss += __shfl_xor_sync(0xffffffffu, ss, o);
    float d = fmaxf(sqrtf(ss), 1e-12f);
    float v0 = x0 / d, v1 = x1 / d;
    __nv_bfloat16 h0 = __float2bfloat16(v0), h1 = __float2bfloat16(v1);
    hi[(size_t)gw * 64 + lane] = h0;
    hi[(size_t)gw * 64 + 32 + lane] = h1;
    lo[(size_t)gw * 64 + lane] = __float2bfloat16(v0 - __bfloat162float(h0));
    lo[(size_t)gw * 64 + 32 + lane] = __float2bfloat16(v1 - __bfloat162float(h1));
}

// ---------------- fp32 small GEMM ----------------
template<int EPI>
__global__ void sgemm_kernel(const float* __restrict__ A, const float* __restrict__ B,
                             float* __restrict__ C, int M, int N, int K,
                             const float* __restrict__ scl, const float* __restrict__ bias)
{
    __shared__ float As[64][17];
    __shared__ float Bs[16][64];
    const int tx = threadIdx.x, ty = threadIdx.y;
    const int tid = ty * 16 + tx;
    const int row0 = blockIdx.y * 64, col0 = blockIdx.x * 64;
    float acc[4][4];
    #pragma unroll
    for (int i = 0; i < 4; i++)
        #pragma unroll
        for (int j = 0; j < 4; j++) acc[i][j] = 0.f;
    const int nt = (K + 15) / 16;
    for (int t = 0; t < nt; t++) {
        const int k0 = t * 16;
        #pragma unroll
        for (int p = 0; p < 4; p++) {
            int i = (tid >> 4) + p * 16, kk = tid & 15;
            int ar = row0 + i, ak = k0 + kk;
            As[i][kk] = (ar < M && ak < K) ? A[(size_t)ar * K + ak] : 0.f;
        }
        #pragma unroll
        for (int p = 0; p < 4; p++) {
            int kk = (tid >> 6) + p * 4, j = tid & 63;
            int bk = k0 + kk, bc = col0 + j;
            Bs[kk][j] = (bk < K && bc < N) ? B[(size_t)bk * N + bc] : 0.f;
        }
        __syncthreads();
        #pragma unroll
        for (int kk = 0; kk < 16; kk++) {
            float a[4];
            #pragma unroll
            for (int i = 0; i < 4; i++) a[i] = As[ty * 4 + i][kk];
            float4 b4 = *reinterpret_cast<const float4*>(&Bs[kk][tx * 4]);
            float b[4] = {b4.x, b4.y, b4.z, b4.w};
            #pragma unroll
            for (int i = 0; i < 4; i++)
                #pragma unroll
                for (int j = 0; j < 4; j++)
                    acc[i][j] = fmaf(a[i], b[j], acc[i][j]);
        }
        __syncthreads();
    }
    #pragma unroll
    for (int i = 0; i < 4; i++) {
        int row = row0 + ty * 4 + i;
        if (row >= M) continue;
        #pragma unroll
        for (int j = 0; j < 4; j++) {
            int col = col0 + tx * 4 + j;
            if (col >= N) continue;
            float v = acc[i][j];
            if (EPI == 5) v = fmaxf(fmaf(scl[col], v, bias[col]), 0.f);
            C[(size_t)row * N + col] = v;
        }
    }
}

// ---------------- sparse agg + misc ----------------
__global__ void agg_kernel_h1(const int* __restrict__ rows, const int* __restrict__ cols,
                              const float* __restrict__ vals, const float* __restrict__ S,
                              float* __restrict__ out)
{
    int e = blockIdx.x;
    int r = rows[e], c = cols[e];
    float v = vals[e];
    const float* src = S + (size_t)c * HH1;
    float* dst = out + (size_t)r * HH1;
    for (int h = threadIdx.x; h < HH1; h += blockDim.x)
        atomicAdd(&dst[h], v * src[h]);
}
__global__ void agg_kernel_h2(const int* __restrict__ rows, const int* __restrict__ cols,
                              const float* __restrict__ vals, const float* __restrict__ S,
                              float* __restrict__ out)
{
    int e = blockIdx.x;
    int r = rows[e], c = cols[e];
    atomicAdd(&out[(size_t)r * HH2 + threadIdx.x], vals[e] * S[(size_t)c * HH2 + threadIdx.x]);
}
__global__ void zero_kernel(float4* __restrict__ p, long long n4)
{
    long long i = (long long)blockIdx.x * blockDim.x + threadIdx.x;
    if (i < n4) p[i] = make_float4(0.f, 0.f, 0.f, 0.f);
}
__global__ void relu_inplace_kernel(float* __restrict__ p, long long n)
{
    long long i = (long long)blockIdx.x * blockDim.x + threadIdx.x;
    if (i < n) p[i] = fmaxf(p[i], 0.f);
}
__global__ void relu_copy_kernel(const float* __restrict__ in, float* __restrict__ out, long long n)
{
    long long i = (long long)blockIdx.x * blockDim.x + threadIdx.x;
    if (i < n) out[i] = fmaxf(in[i], 0.f);
}
__global__ void bnprep_kernel(const float* __restrict__ gamma, const float* __restrict__ beta,
                              const float* __restrict__ mean, const float* __restrict__ var,
                              const float* __restrict__ bd, float* __restrict__ a, float* __restrict__ b)
{
    int j = blockIdx.x * blockDim.x + threadIdx.x;
    if (j >= HH1) return;
    float s = gamma[j] * rsqrtf(var[j] + 1e-5f);
    a[j] = s;
    b[j] = beta[j] + s * (bd[j] - mean[j]);
}
__global__ void g2_kernel(const float* __restrict__ vsum, const float* __restrict__ rsum,
                          float* __restrict__ g2, int M)
{
    int gw = (blockIdx.x * blockDim.x + threadIdx.x) >> 5;
    int lane = threadIdx.x & 31;
    if (gw >= M) return;
    float inv = 1.f / rsum[gw];
    float x0 = vsum[(size_t)gw * 64 + lane] * inv;
    float x1 = vsum[(size_t)gw * 64 + 32 + lane] * inv;
    float ss = x0 * x0 + x1 * x1;
    #pragma unroll
    for (int o = 16; o > 0; o >>= 1) ss += __shfl_xor_sync(0xffffffffu, ss, o);
    float d = fmaxf(sqrtf(ss), 1e-12f);
    g2[(size_t)gw * 64 + lane] = 1.f / (1.f + expf(-x0 / d));
    g2[(size_t)gw * 64 + 32 + lane] = 1.f / (1.f + expf(-x1 / d));
}
__global__ void disc_kernel(const float* __restrict__ emb1, const float* __restrict__ emb3,
                            const float* __restrict__ g2, const float* __restrict__ W,
                            const float* __restrict__ bptr, float* __restrict__ ret, int M)
{
    __shared__ float Ws[64][65];
    int tid = threadIdx.x;
    for (int id = tid; id < 4096; id += 256) Ws[id >> 6][id & 63] = W[id];
    __syncthreads();
    int lane = tid & 31;
    int row = blockIdx.x * 8 + (tid >> 5);
    if (row >= M) return;
    float g0 = g2[(size_t)row * 64 + lane];
    float g1 = g2[(size_t)row * 64 + 32 + lane];
    float ulo = 0.f, uhi = 0.f;
    #pragma unroll
    for (int e = 0; e < 64; e++) {
        float ge = (e < 32) ? __shfl_sync(0xffffffffu, g0, e) : __shfl_sync(0xffffffffu, g1, e - 32);
        ulo = fmaf(Ws[lane][e], ge, ulo);
        uhi = fmaf(Ws[lane + 32][e], ge, uhi);
    }
    float s1 = emb1[(size_t)row * 64 + lane] * ulo + emb1[(size_t)row * 64 + 32 + lane] * uhi;
    float s2 = emb3[(size_t)row * 64 + lane] * ulo + emb3[(size_t)row * 64 + 32 + lane] * uhi;
    #pragma unroll
    for (int o = 16; o > 0; o >>= 1) {
        s1 += __shfl_xor_sync(0xffffffffu, s1, o);
        s2 += __shfl_xor_sync(0xffffffffu, s2, o);
    }
    if (lane == 0) {
        float b = bptr[0];
        ret[(size_t)row * 2 + 0] = s1 + b;
        ret[(size_t)row * 2 + 1] = s2 + b;
    }
}

static inline int cdiv(int a, int b) { return (a + b - 1) / b; }

extern "C" void kernel_launch(void* const* d_in, const int* in_sizes, int n_in,
                              void* d_out, int out_size)
{
    const float* feat   = (const float*)d_in[0];
    const float* feat_a = (const float*)d_in[1];
    const float* feat_b = (const float*)d_in[2];
    const int* adj_rows = (const int*)d_in[3];
    const int* adj_cols = (const int*)d_in[4];
    const float* adj_vals = (const float*)d_in[5];
    const float* graphN = (const float*)d_in[6];
    const float* W1 = (const float*)d_in[7];
    const float* W2 = (const float*)d_in[8];
    const float* Wd = (const float*)d_in[9];
    const float* bd = (const float*)d_in[10];
    const float* bn_gamma = (const float*)d_in[11];
    const float* bn_beta  = (const float*)d_in[12];
    const float* bn_mean  = (const float*)d_in[13];
    const float* bn_var   = (const float*)d_in[14];
    const float* Wpi   = (const float*)d_in[15];
    const float* bpi   = (const float*)d_in[16];
    const float* Wdisp = (const float*)d_in[17];
    const float* bdisp = (const float*)d_in[18];
    const float* Wmean = (const float*)d_in[19];
    const float* bmean = (const float*)d_in[20];
    const float* disc_W = (const float*)d_in[21];
    const float* disc_b = (const float*)d_in[22];
    float* out = (float*)d_out;

    #define SYM(T, v, s) T* v; { void* p_; cudaGetSymbolAddress(&p_, s); v = (T*)p_; }
    SYM(float, S, g_S)  SYM(float, H, g_H)  SYM(float, XD, g_XD)  SYM(float, S2, g_S2)
    SYM(float, E1, g_EMB1) SYM(float, E3, g_EMB3) SYM(float, VS, g_VSUM) SYM(float, G2v, g_G2)
    SYM(float, RS, g_RSUM) SYM(float, BA, g_BNA) SYM(float, BB, g_BNB)
    SYM(__nv_bfloat16, Ah, g_Ah) SYM(__nv_bfloat16, Al, g_Al)
    SYM(__nv_bfloat16, W1th, g_W1th) SYM(__nv_bfloat16, W1tl, g_W1tl)
    SYM(__nv_bfloat16, XDh, g_XDh) SYM(__nv_bfloat16, XDl, g_XDl)
    SYM(__nv_bfloat16, Wpith, g_Wpith) SYM(__nv_bfloat16, Wpitl, g_Wpitl)
    SYM(__nv_bfloat16, Wdth, g_Wdth) SYM(__nv_bfloat16, Wdtl, g_Wdtl)
    SYM(__nv_bfloat16, Wmth, g_Wmth) SYM(__nv_bfloat16, Wmtl, g_Wmtl)
    SYM(__nv_bfloat16, Gh, g_Gh) SYM(__nv_bfloat16, E1th, g_E1th) SYM(__nv_bfloat16, E1tl, g_E1tl)
    SYM(__nv_bfloat16, ZNh, g_ZNh) SYM(__nv_bfloat16, ZNl, g_ZNl)

    const dim3 blk(16, 16);
    const int mt64 = cdiv(NN, 64), mt128 = cdiv(NN, 128);

    // weight conversions
    conv_transpose<<<(unsigned)(((long long)NP_W1 * KP_FIN + 255) / 256), 256>>>(W1, FIN, HH1, KP_FIN, NP_W1, W1th, W1tl, 0);
    conv_transpose<<<(unsigned)(((long long)NP_DEC * KP_H1 + 255) / 256), 256>>>(Wpi, HH1, FIN, KP_H1, NP_DEC, Wpith, Wpitl, 0);
    conv_transpose<<<(unsigned)(((long long)NP_DEC * KP_H1 + 255) / 256), 256>>>(Wdisp, HH1, FIN, KP_H1, NP_DEC, Wdth, Wdtl, 0);
    conv_transpose<<<(unsigned)(((long long)NP_DEC * KP_H1 + 255) / 256), 256>>>(Wmean, HH1, FIN, KP_H1, NP_DEC, Wmth, Wmtl, 0);
    bnprep_kernel<<<cdiv(HH1, 256), 256>>>(bn_gamma, bn_beta, bn_mean, bn_var, bd, BA, BB);

    // encodes
    const float* xs[3] = {feat, feat_a, feat_b};
    const long long zo[3] = {Z1_OFF, Z2_OFF, Z3_OFF};
    for (int s = 0; s < 3; s++) {
        float* z = out + zo[s];
        conv_rows<<<NN, 256>>>(xs[s], FIN, KP_FIN, Ah, Al, nullptr);
        gemm_mma<128, 0, 3><<<dim3(NP_W1 / 128, mt128), 256>>>(
            Ah, Al, KP_FIN, W1th, W1tl, KP_FIN, NP_W1, S, HH1, NN, HH1, KP_FIN, nullptr);
        long long n4 = (long long)NN * HH1 / 4;
        zero_kernel<<<(unsigned)((n4 + 255) / 256), 256>>>((float4*)H, n4);
        agg_kernel_h1<<<NE, 128>>>(adj_rows, adj_cols, adj_vals, S, H);
        relu_inplace_kernel<<<(unsigned)(((long long)NN * HH1 + 255) / 256), 256>>>(H, (long long)NN * HH1);
        sgemm_kernel<0><<<dim3(1, mt64), blk>>>(H, W2, S2, NN, HH2, HH1, nullptr, nullptr);
        long long m4 = (long long)NN * HH2 / 4;
        zero_kernel<<<(unsigned)((m4 + 255) / 256), 256>>>((float4*)z, m4);
        agg_kernel_h2<<<NE, 64>>>(adj_rows, adj_cols, adj_vals, S2, z);
    }
    float* z1 = out + Z1_OFF;
    float* z3 = out + Z3_OFF;

    relu_copy_kernel<<<(unsigned)(((long long)NN * HH2 + 255) / 256), 256>>>(z1, E1, (long long)NN * HH2);
    relu_copy_kernel<<<(unsigned)(((long long)NN * HH2 + 255) / 256), 256>>>(z3, E3, (long long)NN * HH2);

    // ZINB decoder
    sgemm_kernel<5><<<dim3(cdiv(HH1, 64), mt64), blk>>>(z1, Wd, XD, NN, HH1, HH2, BA, BB);
    conv_rows<<<NN, 256>>>(XD, HH1, KP_H1, XDh, XDl, nullptr);
    gemm_mma<128, 2, 3><<<dim3(NP_DEC / 128, mt128), 256>>>(
        XDh, XDl, KP_H1, Wpith, Wpitl, KP_H1, NP_DEC, out + PI_OFF, FIN, NN, FIN, KP_H1, bpi);
    gemm_mma<128, 3, 3><<<dim3(NP_DEC / 128, mt128), 256>>>(
        XDh, XDl, KP_H1, Wdth, Wdtl, KP_H1, NP_DEC, out + DISP_OFF, FIN, NN, FIN, KP_H1, bdisp);
    gemm_mma<128, 4, 3><<<dim3(NP_DEC / 128, mt128), 256>>>(
        XDh, XDl, KP_H1, Wmth, Wmtl, KP_H1, NP_DEC, out + MEAN_OFF, FIN, NN, FIN, KP_H1, bmean);

    // rec_adj = sigmoid(zn @ zn^T)
    znconv_kernel<<<cdiv(NN * 32, 256), 256>>>(z1, ZNh, ZNl, NN);
    gemm_mma<128, 2, 3><<<dim3(cdiv(NN, 128), mt128), 256>>>(
        ZNh, ZNl, 64, ZNh, ZNl, 64, NN, out + REC_OFF, NN, NN, NN, 64, nullptr);

    // readout: vsum = G @ emb1 (G hi-only, emb side hi/lo 2-pass), fused row-sum
    conv_rows<<<NN, 256>>>(graphN, NN, KP_N, Gh, nullptr, RS);
    conv_transpose<<<(unsigned)(((long long)64 * KP_N + 255) / 256), 256>>>(z1, NN, HH2, KP_N, 64, E1th, E1tl, 1);
    gemm_mma<64, 0, 2><<<dim3(1, mt128), 256>>>(
        Gh, nullptr, KP_N, E1th, E1tl, KP_N, 64, VS, HH2, NN, HH2, KP_N, nullptr);
    g2_kernel<<<cdiv(NN * 32, 256), 256>>>(VS, RS, G2v, NN);
    disc_kernel<<<cdiv(NN, 8), 256>>>(E1, E3, G2v, disc_W, disc_b, out + RET_OFF, NN);
}

// round 10
// speedup vs baseline: 2.5933x; 1.5857x over previous
#include <cuda_runtime.h>
#include <cuda_bf16.h>
#include <math.h>
#include <stdint.h>

#define NN   10000
#define FIN  3000
#define HH1  500
#define HH2  64
#define NE   160000
#define KP_FIN 3008
#define KP_H1  512
#define KP_N   10048
#define NP_W1  512
#define NP_DEC 3072

static const long long Z1_OFF   = 0LL;
static const long long Z2_OFF   = 640000LL;
static const long long Z3_OFF   = 1280000LL;
static const long long PI_OFF   = 1920000LL;
static const long long DISP_OFF = 31920000LL;
static const long long MEAN_OFF = 61920000LL;
static const long long REC_OFF  = 91920000LL;
static const long long RET_OFF  = 191920000LL;

__device__ float g_S   [NN * HH1];
__device__ float g_H   [NN * HH1];
__device__ float g_XD  [NN * HH1];
__device__ float g_S2  [NN * HH2];
__device__ float g_EMB1[NN * HH2];
__device__ float g_EMB3[NN * HH2];
__device__ float g_VSUM[NN * HH2];
__device__ float g_G2  [NN * HH2];
__device__ float g_RSUM[NN];
__device__ float g_BNA [HH1];
__device__ float g_BNB [HH1];
__device__ __nv_bfloat16 g_Ah[(size_t)NN * KP_FIN];
__device__ __nv_bfloat16 g_Al[(size_t)NN * KP_FIN];
__device__ __nv_bfloat16 g_W1th[(size_t)NP_W1 * KP_FIN];
__device__ __nv_bfloat16 g_W1tl[(size_t)NP_W1 * KP_FIN];
__device__ __nv_bfloat16 g_XDh[(size_t)NN * KP_H1];
__device__ __nv_bfloat16 g_XDl[(size_t)NN * KP_H1];
__device__ __nv_bfloat16 g_Wpith[(size_t)NP_DEC * KP_H1];
__device__ __nv_bfloat16 g_Wpitl[(size_t)NP_DEC * KP_H1];
__device__ __nv_bfloat16 g_Wdth [(size_t)NP_DEC * KP_H1];
__device__ __nv_bfloat16 g_Wdtl [(size_t)NP_DEC * KP_H1];
__device__ __nv_bfloat16 g_Wmth [(size_t)NP_DEC * KP_H1];
__device__ __nv_bfloat16 g_Wmtl [(size_t)NP_DEC * KP_H1];
__device__ __nv_bfloat16 g_Gh[(size_t)NN * KP_N];
__device__ __nv_bfloat16 g_E1th[(size_t)64 * KP_N];
__device__ __nv_bfloat16 g_E1tl[(size_t)64 * KP_N];
__device__ __nv_bfloat16 g_ZNh[(size_t)NN * 64];
__device__ __nv_bfloat16 g_ZNl[(size_t)NN * 64];
// CSR scratch
__device__ int g_cnt[NN];
__device__ int g_start[NN + 1];
__device__ int g_pos[NN];
__device__ int g_eidx[NE];

// ---------------- helpers ----------------
__device__ __forceinline__ uint32_t smem_u32(const void* p) {
    uint32_t a;
    asm("{ .reg .u64 t; cvta.to.shared.u64 t, %1; cvt.u32.u64 %0, t; }" : "=r"(a) : "l"(p));
    return a;
}
__device__ __forceinline__ void cpa16(uint32_t saddr, const void* g, bool pred) {
    int sz = pred ? 16 : 0;  // src-size 0 => zero-fill 16B
    asm volatile("cp.async.cg.shared.global [%0], [%1], 16, %2;" :: "r"(saddr), "l"(g), "r"(sz) : "memory");
}
__device__ __forceinline__ void ldsm4(uint32_t* r, uint32_t addr) {
    asm volatile("ldmatrix.sync.aligned.m8n8.x4.shared.b16 {%0,%1,%2,%3}, [%4];"
        : "=r"(r[0]), "=r"(r[1]), "=r"(r[2]), "=r"(r[3]) : "r"(addr));
}
__device__ __forceinline__ void mma16816(float* d, const uint32_t* a, const uint32_t* b) {
    asm volatile(
        "mma.sync.aligned.m16n8k16.row.col.f32.bf16.bf16.f32 "
        "{%0,%1,%2,%3}, {%4,%5,%6,%7}, {%8,%9}, {%0,%1,%2,%3};"
        : "+f"(d[0]), "+f"(d[1]), "+f"(d[2]), "+f"(d[3])
        : "r"(a[0]), "r"(a[1]), "r"(a[2]), "r"(a[3]), "r"(b[0]), "r"(b[1]));
}
template<int EPI>
__device__ __forceinline__ float epi_apply(float v, const float* __restrict__ bias, int gc) {
    if (EPI == 2) {
        float x = v + (bias ? bias[gc] : 0.f);
        return 1.f / (1.f + expf(-x));
    } else if (EPI == 3) {
        float x = v + bias[gc];
        float sp = (x > 0.f) ? x + log1pf(expf(-x)) : log1pf(expf(x));
        return fminf(fmaxf(sp, 1e-4f), 1e4f);
    } else if (EPI == 4) {
        return fminf(fmaxf(expf(v + bias[gc]), 1e-5f), 1e6f);
    } else if (EPI == 6) {
        // sigmoid on [-1,1] via odd Taylor (abs err ~2e-6), FFMA-only
        float u = v * v;
        float p = fmaf(u, 2.1357286e-5f, -2.1084563e-4f);
        p = fmaf(u, p, 2.0833334e-3f);
        p = fmaf(u, p, -2.0833333e-2f);
        p = fmaf(u, p, 0.25f);
        return fmaf(v, p, 0.5f);
    }
    return v;
}

// ============================================================
// bf16-split mma.sync GEMM with ldmatrix + 3-stage cp.async.
// C[M,Nreal] = A[M,Kp] @ Bt[NB,Kp]^T.  BM=128, BK=64, 256 thr.
// smem layout per stage: rows of 64 bf16 (128B), 16B chunks XOR-swizzled.
// ============================================================
template<int BN, int EPI, int NPASS>
__global__ void __launch_bounds__(256) gemm_mma(
    const __nv_bfloat16* __restrict__ Ah, const __nv_bfloat16* __restrict__ Al, int lda,
    const __nv_bfloat16* __restrict__ Bh, const __nv_bfloat16* __restrict__ Bl, int ldb, int NB,
    float* __restrict__ C, int ldc, int M, int Nreal, int Kp,
    const float* __restrict__ bias)
{
    constexpr int WN = BN / 4;
    constexpr int NT = WN / 8;
    constexpr int ASTR = 128 * 128;          // 16KB per A stage
    constexpr int BSTR = BN * 128;
    constexpr int BBASE = 3 * ASTR;
    extern __shared__ __align__(16) char dsm[];
    const uint32_t smem = smem_u32(dsm);

    const int tid = threadIdx.x;
    const int wid = tid >> 5, lane = tid & 31;
    const int wm = wid >> 2, wn = wid & 3;
    const int row0 = blockIdx.y * 128, col0 = blockIdx.x * BN;

    const __nv_bfloat16* APP[3] = {Ah, Ah, Al};
    const __nv_bfloat16* BPP[3] = {Bh, Bl, Bh};
    const int KT = Kp >> 6;
    const int S = KT * NPASS;

    float acc[4][NT][4];
    #pragma unroll
    for (int i = 0; i < 4; i++)
        #pragma unroll
        for (int j = 0; j < NT; j++)
            #pragma unroll
            for (int k = 0; k < 4; k++) acc[i][j][k] = 0.f;

    auto load_stage = [&](int s) {
        const int buf = s % 3;
        const int pass = s / KT;
        const int k0 = (s - pass * KT) << 6;
        const __nv_bfloat16* Ap = APP[pass];
        const __nv_bfloat16* Bp = BPP[pass];
        #pragma unroll
        for (int g = tid; g < 1024; g += 256) {
            int r = g >> 3, c = g & 7;
            int gr = row0 + r;
            bool p = (gr < M); if (!p) gr = 0;
            uint32_t sa = smem + buf * ASTR + r * 128 + ((c ^ (r & 7)) << 4);
            cpa16(sa, Ap + (size_t)gr * lda + k0 + c * 8, p);
        }
        #pragma unroll
        for (int g = tid; g < BN * 8; g += 256) {
            int r = g >> 3, c = g & 7;
            int gn = col0 + r;
            bool p = (gn < NB); if (!p) gn = 0;
            uint32_t sa = smem + BBASE + buf * BSTR + r * 128 + ((c ^ (r & 7)) << 4);
            cpa16(sa, Bp + (size_t)gn * ldb + k0 + c * 8, p);
        }
        asm volatile("cp.async.commit_group;" ::: "memory");
    };

    // per-lane fragment source rows (ldmatrix x4 addressing)
    const int swz = lane & 7;
    const int rA = (lane & 7) + (((lane >> 3) & 1) << 3);
    const int hiA = lane >> 4;
    const int rB = (lane & 7) + (((lane >> 4) & 1) << 3);
    const int hiB = (lane >> 3) & 1;

    load_stage(0);
    if (S > 1) load_stage(1);

    for (int s = 0; s < S; s++) {
        if (s + 1 < S) { asm volatile("cp.async.wait_group 1;" ::: "memory"); }
        else           { asm volatile("cp.async.wait_group 0;" ::: "memory"); }
        __syncthreads();
        if (s + 2 < S) load_stage(s + 2);

        const int buf = s % 3;
        const uint32_t aBase = smem + buf * ASTR + (wm * 64 + rA) * 128;
        const uint32_t bBase = smem + BBASE + buf * BSTR + (wn * WN + rB) * 128;

        #pragma unroll
        for (int kk = 0; kk < 4; kk++) {
            uint32_t af[4][4];
            const uint32_t aoff = (((kk * 2 + hiA) ^ swz) << 4);
            #pragma unroll
            for (int mi = 0; mi < 4; mi++)
                ldsm4(af[mi], aBase + mi * 2048 + aoff);
            uint32_t bf[NT][2];
            const uint32_t boff = (((kk * 2 + hiB) ^ swz) << 4);
            #pragma unroll
            for (int np = 0; np < NT / 2; np++) {
                uint32_t t4[4];
                ldsm4(t4, bBase + np * 2048 + boff);
                bf[np * 2][0] = t4[0]; bf[np * 2][1] = t4[1];
                bf[np * 2 + 1][0] = t4[2]; bf[np * 2 + 1][1] = t4[3];
            }
            #pragma unroll
            for (int mi = 0; mi < 4; mi++)
                #pragma unroll
                for (int ni = 0; ni < NT; ni++)
                    mma16816(acc[mi][ni], af[mi], bf[ni]);
        }
        __syncthreads();
    }

    #pragma unroll
    for (int mi = 0; mi < 4; mi++) {
        #pragma unroll
        for (int ni = 0; ni < NT; ni++) {
            int gr = row0 + wm * 64 + mi * 16 + (lane >> 2);
            int gc = col0 + wn * WN + ni * 8 + (lane & 3) * 2;
            #pragma unroll
            for (int h = 0; h < 2; h++) {
                int r = gr + h * 8;
                if (r < M) {
                    if (gc < Nreal)
                        C[(size_t)r * ldc + gc] = epi_apply<EPI>(acc[mi][ni][2 * h], bias, gc);
                    if (gc + 1 < Nreal)
                        C[(size_t)r * ldc + gc + 1] = epi_apply<EPI>(acc[mi][ni][2 * h + 1], bias, gc + 1);
                }
            }
        }
    }
}

// ---------------- conversions ----------------
__global__ void conv_rows(const float* __restrict__ in, int K, int Kp,
                          __nv_bfloat16* __restrict__ hi, __nv_bfloat16* __restrict__ lo,
                          float* __restrict__ rsum)
{
    const int r = blockIdx.x;
    const float* src = in + (size_t)r * K;
    const size_t o = (size_t)r * Kp;
    float s = 0.f;
    for (int c = threadIdx.x; c < Kp; c += 256) {
        float v = (c < K) ? src[c] : 0.f;
        s += v;
        __nv_bfloat16 h = __float2bfloat16(v);
        hi[o + c] = h;
        if (lo) lo[o + c] = __float2bfloat16(v - __bfloat162float(h));
    }
    if (rsum) {
        __shared__ float red[256];
        red[threadIdx.x] = s; __syncthreads();
        for (int st = 128; st > 0; st >>= 1) {
            if (threadIdx.x < st) red[threadIdx.x] += red[threadIdx.x + st];
            __syncthreads();
        }
        if (threadIdx.x == 0) rsum[r] = red[0];
    }
}
__global__ void conv_transpose(const float* __restrict__ W, int K, int N, int Kp, int Np,
                               __nv_bfloat16* __restrict__ hi, __nv_bfloat16* __restrict__ lo,
                               int do_relu)
{
    long long idx = (long long)blockIdx.x * blockDim.x + threadIdx.x;
    if (idx >= (long long)Np * Kp) return;
    int n = (int)(idx / Kp), k = (int)(idx % Kp);
    float v = (n < N && k < K) ? W[(size_t)k * N + n] : 0.f;
    if (do_relu) v = fmaxf(v, 0.f);
    __nv_bfloat16 h = __float2bfloat16(v);
    hi[idx] = h;
    lo[idx] = __float2bfloat16(v - __bfloat162float(h));
}
__global__ void znconv_kernel(const float* __restrict__ z1,
                              __nv_bfloat16* __restrict__ hi, __nv_bfloat16* __restrict__ lo, int M)
{
    int gw = (blockIdx.x * blockDim.x + threadIdx.x) >> 5;
    int lane = threadIdx.x & 31;
    if (gw >= M) return;
    float x0 = z1[(size_t)gw * 64 + lane];
    float x1 = z1[(size_t)gw * 64 + 32 + lane];
    float ss = x0 * x0 + x1 * x1;
    #pragma unroll
    for (int o = 16; o > 0; o >>= 1) ss += __shfl_xor_sync(0xffffffffu, ss, o);
    float d = fmaxf(sqrtf(ss), 1e-12f);
    float v0 = x0 / d, v1 = x1 / d;
    __nv_bfloat16 h0 = __float2bfloat16(v0), h1 = __float2bfloat16(v1);
    hi[(size_t)gw * 64 + lane] = h0;
    hi[(size_t)gw * 64 + 32 + lane] = h1;
    lo[(size_t)gw * 64 + lane] = __float2bfloat16(v0 - __bfloat162float(h0));
    lo[(size_t)gw * 64 + 32 + lane] = __float2bfloat16(v1 - __bfloat162float(h1));
}

// ---------------- CSR build + aggregation (atomic-free accumulate) ----------------
__global__ void zero_int_kernel(int* __restrict__ p, int n) {
    int i = blockIdx.x * blockDim.x + threadIdx.x;
    if (i < n) p[i] = 0;
}
__global__ void hist_kernel(const int* __restrict__ rows, int* __restrict__ cnt) {
    int e = blockIdx.x * blockDim.x + threadIdx.x;
    if (e < NE) atomicAdd(&cnt[rows[e]], 1);
}
__global__ void scan_kernel(const int* __restrict__ cnt, int* __restrict__ start,
                            int* __restrict__ pos, int n)
{
    __shared__ int part[1024];
    const int tid = threadIdx.x;
    const int per = (n + 1023) / 1024;
    const int b0 = tid * per;
    int s = 0;
    for (int i = 0; i < per; i++) { int j = b0 + i; if (j < n) s += cnt[j]; }
    part[tid] = s; __syncthreads();
    for (int off = 1; off < 1024; off <<= 1) {
        int v = (tid >= off) ? part[tid - off] : 0;
        __syncthreads();
        part[tid] += v;
        __syncthreads();
    }
    int excl = (tid == 0) ? 0 : part[tid - 1];
    for (int i = 0; i < per; i++) {
        int j = b0 + i;
        if (j < n) { start[j] = excl; pos[j] = excl; excl += cnt[j]; }
    }
    if (tid == 1023) start[n] = part[1023];
}
__global__ void scatter_kernel(const int* __restrict__ rows, int* __restrict__ pos,
                               int* __restrict__ eidx)
{
    int e = blockIdx.x * blockDim.x + threadIdx.x;
    if (e >= NE) return;
    int p = atomicAdd(&pos[rows[e]], 1);
    eidx[p] = e;
}
__global__ void agg_csr_500(const int* __restrict__ start, const int* __restrict__ eidx,
                            const int* __restrict__ cols, const float* __restrict__ vals,
                            const float* __restrict__ S, float* __restrict__ out, int relu)
{
    const int r = blockIdx.x;
    const int b = start[r], e = start[r + 1];
    const int t = threadIdx.x;  // 256
    float a0 = 0.f, a1 = 0.f;
    for (int i = b; i < e; i++) {
        int ed = __ldg(&eidx[i]);
        int c = __ldg(&cols[ed]);
        float v = __ldg(&vals[ed]);
        const float* src = S + (size_t)c * HH1;
        a0 += v * __ldg(&src[t]);
        if (t + 256 < HH1) a1 += v * __ldg(&src[t + 256]);
    }
    if (relu) { a0 = fmaxf(a0, 0.f); a1 = fmaxf(a1, 0.f); }
    float* dst = out + (size_t)r * HH1;
    dst[t] = a0;
    if (t + 256 < HH1) dst[t + 256] = a1;
}
__global__ void agg_csr_64(const int* __restrict__ start, const int* __restrict__ eidx,
                           const int* __restrict__ cols, const float* __restrict__ vals,
                           const float* __restrict__ S, float* __restrict__ out)
{
    const int r = blockIdx.x * 4 + (threadIdx.x >> 6);
    const int c64 = threadIdx.x & 63;
    if (r >= NN) return;
    const int b = start[r], e = start[r + 1];
    float a = 0.f;
    for (int i = b; i < e; i++) {
        int ed = __ldg(&eidx[i]);
        a += __ldg(&vals[ed]) * __ldg(&S[(size_t)__ldg(&cols[ed]) * HH2 + c64]);
    }
    out[(size_t)r * HH2 + c64] = a;
}

// ---------------- fp32 small GEMM ----------------
template<int EPI>
__global__ void sgemm_kernel(const float* __restrict__ A, const float* __restrict__ B,
                             float* __restrict__ C, int M, int N, int K,
                             const float* __restrict__ scl, const float* __restrict__ bias)
{
    __shared__ float As[64][17];
    __shared__ float Bs[16][64];
    const int tx = threadIdx.x, ty = threadIdx.y;
    const int tid = ty * 16 + tx;
    const int row0 = blockIdx.y * 64, col0 = blockIdx.x * 64;
    float acc[4][4];
    #pragma unroll
    for (int i = 0; i < 4; i++)
        #pragma unroll
        for (int j = 0; j < 4; j++) acc[i][j] = 0.f;
    const int nt = (K + 15) / 16;
    for (int t = 0; t < nt; t++) {
        const int k0 = t * 16;
        #pragma unroll
        for (int p = 0; p < 4; p++) {
            int i = (tid >> 4) + p * 16, kk = tid & 15;
            int ar = row0 + i, ak = k0 + kk;
            As[i][kk] = (ar < M && ak < K) ? A[(size_t)ar * K + ak] : 0.f;
        }
        #pragma unroll
        for (int p = 0; p < 4; p++) {
            int kk = (tid >> 6) + p * 4, j = tid & 63;
            int bk = k0 + kk, bc = col0 + j;
            Bs[kk][j] = (bk < K && bc < N) ? B[(size_t)bk * N + bc] : 0.f;
        }
        __syncthreads();
        #pragma unroll
        for (int kk = 0; kk < 16; kk++) {
            float a[4];
            #pragma unroll
            for (int i = 0; i < 4; i++) a[i] = As[ty * 4 + i][kk];
            float4 b4 = *reinterpret_cast<const float4*>(&Bs[kk][tx * 4]);
            float b[4] = {b4.x, b4.y, b4.z, b4.w};
            #pragma unroll
            for (int i = 0; i < 4; i++)
                #pragma unroll
                for (int j = 0; j < 4; j++)
                    acc[i][j] = fmaf(a[i], b[j], acc[i][j]);
        }
        __syncthreads();
    }
    #pragma unroll
    for (int i = 0; i < 4; i++) {
        int row = row0 + ty * 4 + i;
        if (row >= M) continue;
        #pragma unroll
        for (int j = 0; j < 4; j++) {
            int col = col0 + tx * 4 + j;
            if (col >= N) continue;
            float v = acc[i][j];
            if (EPI == 5) v = fmaxf(fmaf(scl[col], v, bias[col]), 0.f);
            C[(size_t)row * N + col] = v;
        }
    }
}

// ---------------- misc ----------------
__global__ void relu_copy_kernel(const float* __restrict__ in, float* __restrict__ out, long long n)
{
    long long i = (long long)blockIdx.x * blockDim.x + threadIdx.x;
    if (i < n) out[i] = fmaxf(in[i], 0.f);
}
__global__ void bnprep_kernel(const float* __restrict__ gamma, const float* __restrict__ beta,
                              const float* __restrict__ mean, const float* __restrict__ var,
                              const float* __restrict__ bd, float* __restrict__ a, float* __restrict__ b)
{
    int j = blockIdx.x * blockDim.x + threadIdx.x;
    if (j >= HH1) return;
    float s = gamma[j] * rsqrtf(var[j] + 1e-5f);
    a[j] = s;
    b[j] = beta[j] + s * (bd[j] - mean[j]);
}
__global__ void g2_kernel(const float* __restrict__ vsum, const float* __restrict__ rsum,
                          float* __restrict__ g2, int M)
{
    int gw = (blockIdx.x * blockDim.x + threadIdx.x) >> 5;
    int lane = threadIdx.x & 31;
    if (gw >= M) return;
    float inv = 1.f / rsum[gw];
    float x0 = vsum[(size_t)gw * 64 + lane] * inv;
    float x1 = vsum[(size_t)gw * 64 + 32 + lane] * inv;
    float ss = x0 * x0 + x1 * x1;
    #pragma unroll
    for (int o = 16; o > 0; o >>= 1) ss += __shfl_xor_sync(0xffffffffu, ss, o);
    float d = fmaxf(sqrtf(ss), 1e-12f);
    g2[(size_t)gw * 64 + lane] = 1.f / (1.f + expf(-x0 / d));
    g2[(size_t)gw * 64 + 32 + lane] = 1.f / (1.f + expf(-x1 / d));
}
__global__ void disc_kernel(const float* __restrict__ emb1, const float* __restrict__ emb3,
                            const float* __restrict__ g2, const float* __restrict__ W,
                            const float* __restrict__ bptr, float* __restrict__ ret, int M)
{
    __shared__ float Ws[64][65];
    int tid = threadIdx.x;
    for (int id = tid; id < 4096; id += 256) Ws[id >> 6][id & 63] = W[id];
    __syncthreads();
    int lane = tid & 31;
    int row = blockIdx.x * 8 + (tid >> 5);
    if (row >= M) return;
    float g0 = g2[(size_t)row * 64 + lane];
    float g1 = g2[(size_t)row * 64 + 32 + lane];
    float ulo = 0.f, uhi = 0.f;
    #pragma unroll
    for (int e = 0; e < 64; e++) {
        float ge = (e < 32) ? __shfl_sync(0xffffffffu, g0, e) : __shfl_sync(0xffffffffu, g1, e - 32);
        ulo = fmaf(Ws[lane][e], ge, ulo);
        uhi = fmaf(Ws[lane + 32][e], ge, uhi);
    }
    float s1 = emb1[(size_t)row * 64 + lane] * ulo + emb1[(size_t)row * 64 + 32 + lane] * uhi;
    float s2 = emb3[(size_t)row * 64 + lane] * ulo + emb3[(size_t)row * 64 + 32 + lane] * uhi;
    #pragma unroll
    for (int o = 16; o > 0; o >>= 1) {
        s1 += __shfl_xor_sync(0xffffffffu, s1, o);
        s2 += __shfl_xor_sync(0xffffffffu, s2, o);
    }
    if (lane == 0) {
        float b = bptr[0];
        ret[(size_t)row * 2 + 0] = s1 + b;
        ret[(size_t)row * 2 + 1] = s2 + b;
    }
}

static inline int cdiv(int a, int b) { return (a + b - 1) / b; }

extern "C" void kernel_launch(void* const* d_in, const int* in_sizes, int n_in,
                              void* d_out, int out_size)
{
    const float* feat   = (const float*)d_in[0];
    const float* feat_a = (const float*)d_in[1];
    const float* feat_b = (const float*)d_in[2];
    const int* adj_rows = (const int*)d_in[3];
    const int* adj_cols = (const int*)d_in[4];
    const float* adj_vals = (const float*)d_in[5];
    const float* graphN = (const float*)d_in[6];
    const float* W1 = (const float*)d_in[7];
    const float* W2 = (const float*)d_in[8];
    const float* Wd = (const float*)d_in[9];
    const float* bd = (const float*)d_in[10];
    const float* bn_gamma = (const float*)d_in[11];
    const float* bn_beta  = (const float*)d_in[12];
    const float* bn_mean  = (const float*)d_in[13];
    const float* bn_var   = (const float*)d_in[14];
    const float* Wpi   = (const float*)d_in[15];
    const float* bpi   = (const float*)d_in[16];
    const float* Wdisp = (const float*)d_in[17];
    const float* bdisp = (const float*)d_in[18];
    const float* Wmean = (const float*)d_in[19];
    const float* bmean = (const float*)d_in[20];
    const float* disc_W = (const float*)d_in[21];
    const float* disc_b = (const float*)d_in[22];
    float* out = (float*)d_out;

    #define SYM(T, v, s) T* v; { void* p_; cudaGetSymbolAddress(&p_, s); v = (T*)p_; }
    SYM(float, S, g_S)  SYM(float, H, g_H)  SYM(float, XD, g_XD)  SYM(float, S2, g_S2)
    SYM(float, E1, g_EMB1) SYM(float, E3, g_EMB3) SYM(float, VS, g_VSUM) SYM(float, G2v, g_G2)
    SYM(float, RS, g_RSUM) SYM(float, BA, g_BNA) SYM(float, BB, g_BNB)
    SYM(__nv_bfloat16, Ah, g_Ah) SYM(__nv_bfloat16, Al, g_Al)
    SYM(__nv_bfloat16, W1th, g_W1th) SYM(__nv_bfloat16, W1tl, g_W1tl)
    SYM(__nv_bfloat16, XDh, g_XDh) SYM(__nv_bfloat16, XDl, g_XDl)
    SYM(__nv_bfloat16, Wpith, g_Wpith) SYM(__nv_bfloat16, Wpitl, g_Wpitl)
    SYM(__nv_bfloat16, Wdth, g_Wdth) SYM(__nv_bfloat16, Wdtl, g_Wdtl)
    SYM(__nv_bfloat16, Wmth, g_Wmth) SYM(__nv_bfloat16, Wmtl, g_Wmtl)
    SYM(__nv_bfloat16, Gh, g_Gh) SYM(__nv_bfloat16, E1th, g_E1th) SYM(__nv_bfloat16, E1tl, g_E1tl)
    SYM(__nv_bfloat16, ZNh, g_ZNh) SYM(__nv_bfloat16, ZNl, g_ZNl)
    SYM(int, CNT, g_cnt) SYM(int, START, g_start) SYM(int, POS, g_pos) SYM(int, EIDX, g_eidx)

    const int SM128 = 96 * 1024;   // 3*(16K + 16K)
    const int SM64  = 72 * 1024;   // 3*(16K + 8K)
    cudaFuncSetAttribute(gemm_mma<128,0,3>, cudaFuncAttributeMaxDynamicSharedMemorySize, SM128);
    cudaFuncSetAttribute(gemm_mma<128,2,3>, cudaFuncAttributeMaxDynamicSharedMemorySize, SM128);
    cudaFuncSetAttribute(gemm_mma<128,3,3>, cudaFuncAttributeMaxDynamicSharedMemorySize, SM128);
    cudaFuncSetAttribute(gemm_mma<128,4,3>, cudaFuncAttributeMaxDynamicSharedMemorySize, SM128);
    cudaFuncSetAttribute(gemm_mma<128,6,3>, cudaFuncAttributeMaxDynamicSharedMemorySize, SM128);
    cudaFuncSetAttribute(gemm_mma<64,0,2>,  cudaFuncAttributeMaxDynamicSharedMemorySize, SM64);

    const dim3 blk(16, 16);
    const int mt64 = cdiv(NN, 64), mt128 = cdiv(NN, 128);

    // CSR build
    zero_int_kernel<<<cdiv(NN, 256), 256>>>(CNT, NN);
    hist_kernel<<<cdiv(NE, 256), 256>>>(adj_rows, CNT);
    scan_kernel<<<1, 1024>>>(CNT, START, POS, NN);
    scatter_kernel<<<cdiv(NE, 256), 256>>>(adj_rows, POS, EIDX);

    // weight conversions
    conv_transpose<<<(unsigned)(((long long)NP_W1 * KP_FIN + 255) / 256), 256>>>(W1, FIN, HH1, KP_FIN, NP_W1, W1th, W1tl, 0);
    conv_transpose<<<(unsigned)(((long long)NP_DEC * KP_H1 + 255) / 256), 256>>>(Wpi, HH1, FIN, KP_H1, NP_DEC, Wpith, Wpitl, 0);
    conv_transpose<<<(unsigned)(((long long)NP_DEC * KP_H1 + 255) / 256), 256>>>(Wdisp, HH1, FIN, KP_H1, NP_DEC, Wdth, Wdtl, 0);
    conv_transpose<<<(unsigned)(((long long)NP_DEC * KP_H1 + 255) / 256), 256>>>(Wmean, HH1, FIN, KP_H1, NP_DEC, Wmth, Wmtl, 0);
    bnprep_kernel<<<cdiv(HH1, 256), 256>>>(bn_gamma, bn_beta, bn_mean, bn_var, bd, BA, BB);

    // encodes
    const float* xs[3] = {feat, feat_a, feat_b};
    const long long zo[3] = {Z1_OFF, Z2_OFF, Z3_OFF};
    for (int s = 0; s < 3; s++) {
        float* z = out + zo[s];
        conv_rows<<<NN, 256>>>(xs[s], FIN, KP_FIN, Ah, Al, nullptr);
        gemm_mma<128, 0, 3><<<dim3(NP_W1 / 128, mt128), 256, SM128>>>(
            Ah, Al, KP_FIN, W1th, W1tl, KP_FIN, NP_W1, S, HH1, NN, HH1, KP_FIN, nullptr);
        agg_csr_500<<<NN, 256>>>(START, EIDX, adj_cols, adj_vals, S, H, 1);
        sgemm_kernel<0><<<dim3(1, mt64), blk>>>(H, W2, S2, NN, HH2, HH1, nullptr, nullptr);
        agg_csr_64<<<cdiv(NN, 4), 256>>>(START, EIDX, adj_cols, adj_vals, S2, z);
    }
    float* z1 = out + Z1_OFF;
    float* z3 = out + Z3_OFF;

    relu_copy_kernel<<<(unsigned)(((long long)NN * HH2 + 255) / 256), 256>>>(z1, E1, (long long)NN * HH2);
    relu_copy_kernel<<<(unsigned)(((long long)NN * HH2 + 255) / 256), 256>>>(z3, E3, (long long)NN * HH2);

    // ZINB decoder
    sgemm_kernel<5><<<dim3(cdiv(HH1, 64), mt64), blk>>>(z1, Wd, XD, NN, HH1, HH2, BA, BB);
    conv_rows<<<NN, 256>>>(XD, HH1, KP_H1, XDh, XDl, nullptr);
    gemm_mma<128, 2, 3><<<dim3(NP_DEC / 128, mt128), 256, SM128>>>(
        XDh, XDl, KP_H1, Wpith, Wpitl, KP_H1, NP_DEC, out + PI_OFF, FIN, NN, FIN, KP_H1, bpi);
    gemm_mma<128, 3, 3><<<dim3(NP_DEC / 128, mt128), 256, SM128>>>(
        XDh, XDl, KP_H1, Wdth, Wdtl, KP_H1, NP_DEC, out + DISP_OFF, FIN, NN, FIN, KP_H1, bdisp);
    gemm_mma<128, 4, 3><<<dim3(NP_DEC / 128, mt128), 256, SM128>>>(
        XDh, XDl, KP_H1, Wmth, Wmtl, KP_H1, NP_DEC, out + MEAN_OFF, FIN, NN, FIN, KP_H1, bmean);

    // rec_adj = sigmoid(zn @ zn^T) with polynomial sigmoid (inputs in [-1,1])
    znconv_kernel<<<cdiv(NN * 32, 256), 256>>>(z1, ZNh, ZNl, NN);
    gemm_mma<128, 6, 3><<<dim3(cdiv(NN, 128), mt128), 256, SM128>>>(
        ZNh, ZNl, 64, ZNh, ZNl, 64, NN, out + REC_OFF, NN, NN, NN, 64, nullptr);

    // readout: vsum = G @ emb1 (G hi-only, emb side hi/lo 2-pass), fused row-sum
    conv_rows<<<NN, 256>>>(graphN, NN, KP_N, Gh, nullptr, RS);
    conv_transpose<<<(unsigned)(((long long)64 * KP_N + 255) / 256), 256>>>(z1, NN, HH2, KP_N, 64, E1th, E1tl, 1);
    gemm_mma<64, 0, 2><<<dim3(1, mt128), 256, SM64>>>(
        Gh, nullptr, KP_N, E1th, E1tl, KP_N, 64, VS, HH2, NN, HH2, KP_N, nullptr);
    g2_kernel<<<cdiv(NN * 32, 256), 256>>>(VS, RS, G2v, NN);
    disc_kernel<<<cdiv(NN, 8), 256>>>(E1, E3, G2v, disc_W, disc_b, out + RET_OFF, NN);
}